// round 9
// baseline (speedup 1.0000x reference)
#include <cuda_runtime.h>
#include <cstdint>
#include <math.h>

#define ALPHA 1000.0f
#define NB 8192
#define ND 784
#define NH 256
#define NE 32
#define NK 512

// ---------------------------------------------------------------------------
// Fragment-major hi/lo scratch (allocation-free rule: __device__ globals).
// A-frag layout: [mblk][KB][32 lanes][4]  (128 floats / block)
// B-frag layout: [nblk][KB][32 lanes][2]  (64 floats / block)
// ---------------------------------------------------------------------------
__device__ float g_xhi [NB * ND], g_xlo [NB * ND];     // x    A-frags, KB=98
__device__ float g_hhi [NB * NH], g_hlo [NB * NH];     // h    A-frags, KB=32
__device__ float g_ehi [NB * NE], g_elo [NB * NE];     // emb  A-frags, KB=4
__device__ float g_h2hi[NB * NH], g_h2lo[NB * NH];     // h2   A-frags, KB=32
__device__ float g_w1hi[32 * 98 * 64],  g_w1lo[32 * 98 * 64];    // W1 (N=256)
__device__ float g_w2hi[4 * 32 * 64],   g_w2lo[4 * 32 * 64];     // W2 (NPAD=32)
__device__ float g_w3hi[32 * 4 * 64],   g_w3lo[32 * 4 * 64];     // W3 (N=256)
__device__ float g_w4hi[112 * 32 * 64], g_w4lo[112 * 32 * 64];   // W4 (NPAD=896)

// ---------------------------------------------------------------------------
// helpers (baseline PTX only)
// ---------------------------------------------------------------------------
__device__ __forceinline__ uint32_t tf32_round(float x) {
    uint32_t u;
    asm("cvt.rna.tf32.f32 %0, %1;" : "=r"(u) : "f"(x));
    return u;
}
__device__ __forceinline__ void mma_tf32(float* d, const uint32_t* a, const uint32_t* b) {
    asm volatile(
        "mma.sync.aligned.m16n8k8.row.col.f32.tf32.tf32.f32 "
        "{%0,%1,%2,%3}, {%4,%5,%6,%7}, {%8,%9}, {%0,%1,%2,%3};"
        : "+f"(d[0]), "+f"(d[1]), "+f"(d[2]), "+f"(d[3])
        : "r"(a[0]), "r"(a[1]), "r"(a[2]), "r"(a[3]), "r"(b[0]), "r"(b[1]));
}
__device__ __forceinline__ uint32_t smem_u32(const void* p) {
    uint32_t a;
    asm("{ .reg .u64 t; cvta.to.shared.u64 t, %1; cvt.u32.u64 %0, t; }" : "=r"(a) : "l"(p));
    return a;
}
__device__ __forceinline__ void cp16(uint32_t dst, const void* src) {
    asm volatile("cp.async.cg.shared.global [%0], [%1], 16;" :: "r"(dst), "l"(src));
}

// write one value into A-fragment hi/lo buffers (for the next GEMM)
__device__ __forceinline__ void write_frag(float v, int m, int k, int KB,
                                           float* ghi, float* glo) {
    uint32_t hi = tf32_round(v);
    uint32_t lo = tf32_round(v - __uint_as_float(hi));
    const int mblk = m >> 4, kblk = k >> 3;
    const int ln   = ((m & 7) << 2) | (k & 3);
    const int slot = ((m >> 3) & 1) | (((k >> 2) & 1) << 1);
    const size_t o = (((size_t)mblk * KB + kblk) * 32 + ln) * 4 + slot;
    ((uint32_t*)ghi)[o] = hi;
    ((uint32_t*)glo)[o] = lo;
}

// ---------------------------------------------------------------------------
// split_A: A[M,K] row-major -> hi/lo A-fragments. Tile 32m x 64k per block.
// ---------------------------------------------------------------------------
__global__ __launch_bounds__(256) void split_A_kernel(
    const float* __restrict__ A, float* __restrict__ hi, float* __restrict__ lo,
    int K, int KB)
{
    __shared__ float s[32][65];
    const int tid = threadIdx.x;
    const int k0 = blockIdx.x * 64;
    const int m0 = blockIdx.y * 32;
#pragma unroll
    for (int i = 0; i < 8; i++) {
        const int idx = tid + i * 256;
        const int r = idx >> 6, cc = idx & 63;
        const int k = k0 + cc;
        s[r][cc] = (k < K) ? A[(size_t)(m0 + r) * K + k] : 0.f;
    }
    __syncthreads();
    const int mblk0 = blockIdx.y * 2, kblk0 = blockIdx.x * 8;
#pragma unroll
    for (int i = 0; i < 2; i++) {
        const int slot = tid + i * 256;       // 0..511
        const int mb = slot >> 8, kb = (slot >> 5) & 7, ln = slot & 31;
        if (kblk0 + kb < KB) {
            const int gg = ln >> 2, cc = ln & 3;
            const int mr = mb * 16 + gg, kc = kb * 8 + cc;
            const float v0 = s[mr][kc],     v1 = s[mr + 8][kc];
            const float v2 = s[mr][kc + 4], v3 = s[mr + 8][kc + 4];
            uint4 h4, l4;
            h4.x = tf32_round(v0); l4.x = tf32_round(v0 - __uint_as_float(h4.x));
            h4.y = tf32_round(v1); l4.y = tf32_round(v1 - __uint_as_float(h4.y));
            h4.z = tf32_round(v2); l4.z = tf32_round(v2 - __uint_as_float(h4.z));
            h4.w = tf32_round(v3); l4.w = tf32_round(v3 - __uint_as_float(h4.w));
            const size_t o = (((size_t)(mblk0 + mb) * KB + kblk0 + kb) * 32 + ln) * 4;
            *(uint4*)&hi[o] = h4;
            *(uint4*)&lo[o] = l4;
        }
    }
}

// ---------------------------------------------------------------------------
// merged split_B for all 4 weights: W[K,N] -> hi/lo B-fragments (pad to NPAD).
// blockIdx.z selects the weight; oversized blocks exit early.
// ---------------------------------------------------------------------------
struct SplitBArgs {
    const float* W[4];
    float* hi[4];
    float* lo[4];
    int K[4], N[4], KB[4], gx[4], gy[4];
};

__global__ __launch_bounds__(256) void split_B4_kernel(SplitBArgs a)
{
    const int z = blockIdx.z;
    if ((int)blockIdx.x >= a.gx[z] || (int)blockIdx.y >= a.gy[z]) return;
    const float* __restrict__ W = a.W[z];
    float* __restrict__ hi = a.hi[z];
    float* __restrict__ lo = a.lo[z];
    const int K = a.K[z], N = a.N[z], KB = a.KB[z];

    __shared__ float s[64][33];
    const int tid = threadIdx.x;
    const int n0 = blockIdx.x * 32;
    const int k0 = blockIdx.y * 64;
#pragma unroll
    for (int i = 0; i < 8; i++) {
        const int idx = tid + i * 256;
        const int r = idx >> 5, cc = idx & 31;
        const int k = k0 + r, n = n0 + cc;
        s[r][cc] = (k < K && n < N) ? W[(size_t)k * N + n] : 0.f;
    }
    __syncthreads();
    const int nblk0 = blockIdx.x * 4, kblk0 = blockIdx.y * 8;
#pragma unroll
    for (int i = 0; i < 4; i++) {
        const int slot = tid + i * 256;       // 0..1023
        const int nb = slot >> 8, kb = (slot >> 5) & 7, ln = slot & 31;
        if (kblk0 + kb < KB) {
            const int gg = ln >> 2, cc = ln & 3;
            const float b0 = s[kb * 8 + cc][nb * 8 + gg];
            const float b1 = s[kb * 8 + cc + 4][nb * 8 + gg];
            uint2 h2, l2;
            h2.x = tf32_round(b0); l2.x = tf32_round(b0 - __uint_as_float(h2.x));
            h2.y = tf32_round(b1); l2.y = tf32_round(b1 - __uint_as_float(h2.y));
            const size_t o = (((size_t)(nblk0 + nb) * KB + kblk0 + kb) * 32 + ln) * 2;
            *(uint2*)&hi[o] = h2;
            *(uint2*)&lo[o] = l2;
        }
    }
}

// ---------------------------------------------------------------------------
// 3xTF32 GEMM on pre-split fragments, cp.async double-buffered.
// CTA tile (MBLKS*16) x (NBLKS*8), 256 threads = 8 warps (2M x 4N),
// K-chunk 16. smem: 2 stages x 32KB fixed sections.
// OUTMODE: 0 = normal C, 1 = A-frags of next gemm, 2 = both.
// ---------------------------------------------------------------------------
#define GEMM_SMEM 65536

template <bool RELU, int OUTMODE, int NBLKS, int MBLKS>
__global__ __launch_bounds__(256, 2) void mma_gemm(
    const float* __restrict__ Ahi, const float* __restrict__ Alo,
    const float* __restrict__ Bhi, const float* __restrict__ Blo,
    const float* __restrict__ bias,
    float* __restrict__ Cn, float* __restrict__ Chi, float* __restrict__ Clo,
    int N, int KB, int KBOUT)
{
    constexpr int NTW = NBLKS / 4;    // nblks per warp
    constexpr int MT  = MBLKS / 2;    // mtiles (16 rows each) per warp
    extern __shared__ char smem[];
    const uint32_t sb32 = smem_u32(smem);
    const int tid = threadIdx.x, wid = tid >> 5, lane = tid & 31;
    const int wm = wid & 1, wn = wid >> 1;
    const int g = lane >> 2, c = lane & 3;
    const int m0 = blockIdx.y * MBLKS * 16, n0 = blockIdx.x * NBLKS * 8;
    const int mblk0 = blockIdx.y * MBLKS, nblk0 = blockIdx.x * NBLKS;

    float acc[MT][NTW][4];
#pragma unroll
    for (int mt = 0; mt < MT; mt++)
#pragma unroll
        for (int nt = 0; nt < NTW; nt++)
#pragma unroll
            for (int i = 0; i < 4; i++) acc[mt][nt][i] = 0.f;

    const int nch = KB >> 1;

    auto issue = [&](int t) {
        const uint32_t s = sb32 + (t & 1) * 32768;
        const int kb0 = t * 2;
        // A: MBLKS*64 cp16 (MBLKS mblks x 2 kblks x 128 floats)
#pragma unroll
        for (int idx = tid; idx < MBLKS * 64; idx += 256) {
            const int mb = idx >> 6, off = idx & 63;
            const size_t go = ((size_t)(mblk0 + mb) * KB + kb0) * 128 + off * 4;
            cp16(s + idx * 16,        Ahi + go);
            cp16(s + 8192 + idx * 16, Alo + go);
        }
        // B: NBLKS*32 cp16 (NBLKS nblks x 2 kblks x 64 floats)
#pragma unroll
        for (int idx = tid; idx < NBLKS * 32; idx += 256) {
            const int nb = idx >> 5, off = idx & 31;
            const size_t go = ((size_t)(nblk0 + nb) * KB + kb0) * 64 + off * 4;
            cp16(s + 16384 + idx * 16, Bhi + go);
            cp16(s + 24576 + idx * 16, Blo + go);
        }
    };

    issue(0);
    asm volatile("cp.async.commit_group;");

    for (int t = 0; t < nch; t++) {
        if (t + 1 < nch) {
            issue(t + 1);
            asm volatile("cp.async.commit_group;");
            asm volatile("cp.async.wait_group 1;");
        } else {
            asm volatile("cp.async.wait_group 0;");
        }
        __syncthreads();

        const char* s = smem + (t & 1) * 32768;
#pragma unroll
        for (int ks = 0; ks < 2; ks++) {
            uint4 ah[MT], al[MT];
#pragma unroll
            for (int mt = 0; mt < MT; mt++) {
                const int off = (((wm * MT + mt) * 2 + ks) * 32 + lane) * 16;
                ah[mt] = *(const uint4*)(s + off);
                al[mt] = *(const uint4*)(s + 8192 + off);
            }
            uint2 bh[NTW], bl[NTW];
#pragma unroll
            for (int nt = 0; nt < NTW; nt++) {
                const int off = (((wn * NTW + nt) * 2 + ks) * 32 + lane) * 8;
                bh[nt] = *(const uint2*)(s + 16384 + off);
                bl[nt] = *(const uint2*)(s + 24576 + off);
            }
#pragma unroll
            for (int mt = 0; mt < MT; mt++)
#pragma unroll
                for (int nt = 0; nt < NTW; nt++) {
                    mma_tf32(acc[mt][nt], (const uint32_t*)&ah[mt], (const uint32_t*)&bh[nt]);
                    mma_tf32(acc[mt][nt], (const uint32_t*)&ah[mt], (const uint32_t*)&bl[nt]);
                    mma_tf32(acc[mt][nt], (const uint32_t*)&al[mt], (const uint32_t*)&bh[nt]);
                }
        }
        __syncthreads();
    }

    // ---- epilogue ----
#pragma unroll
    for (int nt = 0; nt < NTW; nt++) {
        const int col = n0 + (wn * NTW + nt) * 8 + 2 * c;
        if (col < N) {
            const float bx = __ldg(&bias[col]);
            const float by = __ldg(&bias[col + 1]);
#pragma unroll
            for (int mt = 0; mt < MT; mt++) {
                const int row = m0 + (wm * MT + mt) * 16 + g;
                float v00 = acc[mt][nt][0] + bx;
                float v01 = acc[mt][nt][1] + by;
                float v10 = acc[mt][nt][2] + bx;
                float v11 = acc[mt][nt][3] + by;
                if (RELU) {
                    v00 = fmaxf(v00, 0.f); v01 = fmaxf(v01, 0.f);
                    v10 = fmaxf(v10, 0.f); v11 = fmaxf(v11, 0.f);
                }
                if (OUTMODE == 0 || OUTMODE == 2) {
                    *(float2*)&Cn[(size_t)row * N + col]       = make_float2(v00, v01);
                    *(float2*)&Cn[(size_t)(row + 8) * N + col] = make_float2(v10, v11);
                }
                if (OUTMODE == 1 || OUTMODE == 2) {
                    write_frag(v00, row,     col,     KBOUT, Chi, Clo);
                    write_frag(v01, row,     col + 1, KBOUT, Chi, Clo);
                    write_frag(v10, row + 8, col,     KBOUT, Chi, Clo);
                    write_frag(v11, row + 8, col + 1, KBOUT, Chi, Clo);
                }
            }
        }
    }
}

// ---------------------------------------------------------------------------
// Fused distances + stable softmin, warp-per-row.
// Block = 256 threads (8 warps), 64 rows/block over 8 passes.
// Lane owns 16 clusters (k = j*32 + lane): 128B-coalesced stores.
// reps + all 64 emb rows staged once; single __syncthreads; shuffle reductions.
// ---------------------------------------------------------------------------
#define REPS_STRIDE 36
#define DIST_SMEM_FLOATS (NK * REPS_STRIDE + 64 * NE)

__global__ __launch_bounds__(256) void dist_softmin_kernel(
    const float* __restrict__ emb, const float* __restrict__ reps,
    float* __restrict__ weighted, float* __restrict__ distances)
{
    extern __shared__ float s[];
    float* reps_s = s;                       // NK * 36
    float* emb_s  = s + NK * REPS_STRIDE;    // 64 * 32

    const int tid  = threadIdx.x;
    const int wid  = tid >> 5;
    const int lane = tid & 31;
    const int brow = blockIdx.x * 64;

    // stage cluster reps (512 x 32, padded stride 36: 9 float4/row, conflict-free)
    const float4* repsg = (const float4*)reps;
    for (int idx = tid; idx < NK * NE / 4; idx += 256) {
        const int k  = idx >> 3;
        const int e4 = idx & 7;
        ((float4*)&reps_s[k * REPS_STRIDE])[e4] = repsg[idx];
    }
    // stage 64 embedding rows
    const float4* embg = (const float4*)(emb + (size_t)brow * NE);
    for (int idx = tid; idx < 64 * NE / 4; idx += 256)
        ((float4*)emb_s)[idx] = embg[idx];
    __syncthreads();

#pragma unroll 1
    for (int pass = 0; pass < 8; pass++) {
        const int r = pass * 8 + wid;

        float er[NE];
#pragma unroll
        for (int e = 0; e < NE; e++) er[e] = emb_s[r * NE + e];   // warp broadcast

        float pd[16];
        float pmin = 3.4e38f;
#pragma unroll
        for (int j = 0; j < 16; j++) {
            const int k = j * 32 + lane;
            const float4* rp = (const float4*)&reps_s[k * REPS_STRIDE];
            float acc = 0.f;
#pragma unroll
            for (int e4 = 0; e4 < 8; e4++) {
                float4 r4 = rp[e4];
                float d0 = er[e4 * 4 + 0] - r4.x;
                float d1 = er[e4 * 4 + 1] - r4.y;
                float d2 = er[e4 * 4 + 2] - r4.z;
                float d3 = er[e4 * 4 + 3] - r4.w;
                acc += d0 * d0; acc += d1 * d1; acc += d2 * d2; acc += d3 * d3;
            }
            pd[j] = acc;
            pmin = fminf(pmin, acc);
        }

        // warp-wide min
#pragma unroll
        for (int o = 16; o > 0; o >>= 1)
            pmin = fminf(pmin, __shfl_xor_sync(0xFFFFFFFF, pmin, o));

        float pe[16];
        float psum = 0.f;
#pragma unroll
        for (int j = 0; j < 16; j++) {
            pe[j] = expf(-ALPHA * (pd[j] - pmin));
            psum += pe[j];
        }
#pragma unroll
        for (int o = 16; o > 0; o >>= 1)
            psum += __shfl_xor_sync(0xFFFFFFFF, psum, o);
        const float inv = 1.0f / psum;

        const size_t base = (size_t)(brow + r) * NK;
#pragma unroll
        for (int j = 0; j < 16; j++) {
            const int k = j * 32 + lane;
            const float dv = pd[j];
            distances[base + k] = dv;
            weighted[base + k]  = dv * pe[j] * inv;
        }
    }
}

// ---------------------------------------------------------------------------
extern "C" void kernel_launch(void* const* d_in, const int* in_sizes, int n_in,
                              void* d_out, int out_size)
{
    const float* x    = (const float*)d_in[0];
    const float* reps = (const float*)d_in[1];
    const float* W1   = (const float*)d_in[2];
    const float* b1   = (const float*)d_in[3];
    const float* W2   = (const float*)d_in[4];
    const float* b2   = (const float*)d_in[5];
    const float* W3   = (const float*)d_in[6];
    const float* b3   = (const float*)d_in[7];
    const float* W4   = (const float*)d_in[8];
    const float* b4   = (const float*)d_in[9];

    float* out       = (float*)d_out;
    float* weighted  = out;
    float* distances = out + (size_t)NB * NK;
    float* rec       = out + 2 * (size_t)NB * NK;
    float* emb       = out + 2 * (size_t)NB * NK + (size_t)NB * ND;

    float *xhi, *xlo, *hhi, *hlo, *ehi, *elo, *h2hi, *h2lo;
    float *w1hi, *w1lo, *w2hi, *w2lo, *w3hi, *w3lo, *w4hi, *w4lo;
    cudaGetSymbolAddress((void**)&xhi,  g_xhi);  cudaGetSymbolAddress((void**)&xlo,  g_xlo);
    cudaGetSymbolAddress((void**)&hhi,  g_hhi);  cudaGetSymbolAddress((void**)&hlo,  g_hlo);
    cudaGetSymbolAddress((void**)&ehi,  g_ehi);  cudaGetSymbolAddress((void**)&elo,  g_elo);
    cudaGetSymbolAddress((void**)&h2hi, g_h2hi); cudaGetSymbolAddress((void**)&h2lo, g_h2lo);
    cudaGetSymbolAddress((void**)&w1hi, g_w1hi); cudaGetSymbolAddress((void**)&w1lo, g_w1lo);
    cudaGetSymbolAddress((void**)&w2hi, g_w2hi); cudaGetSymbolAddress((void**)&w2lo, g_w2lo);
    cudaGetSymbolAddress((void**)&w3hi, g_w3hi); cudaGetSymbolAddress((void**)&w3lo, g_w3lo);
    cudaGetSymbolAddress((void**)&w4hi, g_w4hi); cudaGetSymbolAddress((void**)&w4lo, g_w4lo);

    cudaFuncSetAttribute((const void*)mma_gemm<true, 1, 8, 8>,
                         cudaFuncAttributeMaxDynamicSharedMemorySize, GEMM_SMEM);
    cudaFuncSetAttribute((const void*)mma_gemm<false, 2, 4, 4>,
                         cudaFuncAttributeMaxDynamicSharedMemorySize, GEMM_SMEM);
    cudaFuncSetAttribute((const void*)mma_gemm<false, 0, 16, 8>,
                         cudaFuncAttributeMaxDynamicSharedMemorySize, GEMM_SMEM);
    const int dist_smem = DIST_SMEM_FLOATS * (int)sizeof(float);
    cudaFuncSetAttribute(dist_softmin_kernel,
                         cudaFuncAttributeMaxDynamicSharedMemorySize, dist_smem);

    // ---- operand pre-splits ----
    split_A_kernel<<<dim3(13, NB / 32), 256>>>(x, xhi, xlo, ND, 98);
    {
        SplitBArgs a;
        a.W[0] = W1;   a.hi[0] = w1hi; a.lo[0] = w1lo;
        a.K[0] = ND;   a.N[0] = NH;    a.KB[0] = 98; a.gx[0] = 8;  a.gy[0] = 13;
        a.W[1] = W2;   a.hi[1] = w2hi; a.lo[1] = w2lo;
        a.K[1] = NH;   a.N[1] = NE;    a.KB[1] = 32; a.gx[1] = 1;  a.gy[1] = 4;
        a.W[2] = W3;   a.hi[2] = w3hi; a.lo[2] = w3lo;
        a.K[2] = NE;   a.N[2] = NH;    a.KB[2] = 4;  a.gx[2] = 8;  a.gy[2] = 1;
        a.W[3] = W4;   a.hi[3] = w4hi; a.lo[3] = w4lo;
        a.K[3] = NH;   a.N[3] = ND;    a.KB[3] = 32; a.gx[3] = 28; a.gy[3] = 4;
        split_B4_kernel<<<dim3(28, 13, 4), 256>>>(a);
    }

    // ---- GEMM chain ----
    // h = relu(x @ W1 + b1)  -> h fragments          (128x64 tiles, 256 CTAs)
    mma_gemm<true, 1, 8, 8><<<dim3(4, NB / 128), 256, GEMM_SMEM>>>(
        xhi, xlo, w1hi, w1lo, b1, nullptr, hhi, hlo, NH, 98, 32);
    // emb = h @ W2 + b2      -> normal emb + emb fragments (64x32 tiles, 128 CTAs)
    mma_gemm<false, 2, 4, 4><<<dim3(1, NB / 64), 256, GEMM_SMEM>>>(
        hhi, hlo, w2hi, w2lo, b2, emb, ehi, elo, NE, 32, 4);
    // h2 = relu(emb @ W3 + b3) -> h2 fragments       (128x64 tiles, 256 CTAs)
    mma_gemm<true, 1, 8, 8><<<dim3(4, NB / 128), 256, GEMM_SMEM>>>(
        ehi, elo, w3hi, w3lo, b3, nullptr, h2hi, h2lo, NH, 4, 32);
    // rec = h2 @ W4 + b4     -> normal output        (128x128 tiles, 448 CTAs)
    mma_gemm<false, 0, 16, 8><<<dim3(7, NB / 128), 256, GEMM_SMEM>>>(
        h2hi, h2lo, w4hi, w4lo, b4, rec, nullptr, nullptr, ND, 32, 0);

    // ---- distances + softmin ----
    dist_softmin_kernel<<<NB / 64, 256, dist_smem>>>(emb, reps, weighted, distances);
}

// round 10
// speedup vs baseline: 1.2062x; 1.2062x over previous
#include <cuda_runtime.h>
#include <cstdint>
#include <math.h>

#define ALPHA 1000.0f
#define NB 8192
#define ND 784
#define NH 256
#define NE 32
#define NK 512

// ---------------------------------------------------------------------------
// Fragment-major hi/lo scratch (allocation-free rule: __device__ globals).
// A-frag layout: [mblk][KB][32 lanes][4]  (128 floats / block)
// B-frag layout: [nblk][KB][32 lanes][2]  (64 floats / block)
// ---------------------------------------------------------------------------
__device__ float g_xhi [NB * ND], g_xlo [NB * ND];     // x    A-frags, KB=98
__device__ float g_hhi [NB * NH], g_hlo [NB * NH];     // h    A-frags, KB=32
__device__ float g_ehi [NB * NE], g_elo [NB * NE];     // emb  A-frags, KB=4
__device__ float g_h2hi[NB * NH], g_h2lo[NB * NH];     // h2   A-frags, KB=32
__device__ float g_w1hi[32 * 98 * 64],  g_w1lo[32 * 98 * 64];    // W1 (N=256)
__device__ float g_w2hi[4 * 32 * 64],   g_w2lo[4 * 32 * 64];     // W2 (NPAD=32)
__device__ float g_w3hi[32 * 4 * 64],   g_w3lo[32 * 4 * 64];     // W3 (N=256)
__device__ float g_w4hi[112 * 32 * 64], g_w4lo[112 * 32 * 64];   // W4 (NPAD=896)

// ---------------------------------------------------------------------------
// helpers (baseline PTX only)
// ---------------------------------------------------------------------------
__device__ __forceinline__ uint32_t tf32_round(float x) {
    uint32_t u;
    asm("cvt.rna.tf32.f32 %0, %1;" : "=r"(u) : "f"(x));
    return u;
}
__device__ __forceinline__ void mma_tf32(float* d, const uint32_t* a, const uint32_t* b) {
    asm volatile(
        "mma.sync.aligned.m16n8k8.row.col.f32.tf32.tf32.f32 "
        "{%0,%1,%2,%3}, {%4,%5,%6,%7}, {%8,%9}, {%0,%1,%2,%3};"
        : "+f"(d[0]), "+f"(d[1]), "+f"(d[2]), "+f"(d[3])
        : "r"(a[0]), "r"(a[1]), "r"(a[2]), "r"(a[3]), "r"(b[0]), "r"(b[1]));
}
__device__ __forceinline__ uint32_t smem_u32(const void* p) {
    uint32_t a;
    asm("{ .reg .u64 t; cvta.to.shared.u64 t, %1; cvt.u32.u64 %0, t; }" : "=r"(a) : "l"(p));
    return a;
}
__device__ __forceinline__ void cp16(uint32_t dst, const void* src) {
    asm volatile("cp.async.cg.shared.global [%0], [%1], 16;" :: "r"(dst), "l"(src));
}

// write one value into A-fragment hi/lo buffers (for the next GEMM)
__device__ __forceinline__ void write_frag(float v, int m, int k, int KB,
                                           float* ghi, float* glo) {
    uint32_t hi = tf32_round(v);
    uint32_t lo = tf32_round(v - __uint_as_float(hi));
    const int mblk = m >> 4, kblk = k >> 3;
    const int ln   = ((m & 7) << 2) | (k & 3);
    const int slot = ((m >> 3) & 1) | (((k >> 2) & 1) << 1);
    const size_t o = (((size_t)mblk * KB + kblk) * 32 + ln) * 4 + slot;
    ((uint32_t*)ghi)[o] = hi;
    ((uint32_t*)glo)[o] = lo;
}

// ---------------------------------------------------------------------------
// split_A: A[M,K] row-major -> hi/lo A-fragments. Tile 32m x 64k per block.
// ---------------------------------------------------------------------------
__global__ __launch_bounds__(256) void split_A_kernel(
    const float* __restrict__ A, float* __restrict__ hi, float* __restrict__ lo,
    int K, int KB)
{
    __shared__ float s[32][65];
    const int tid = threadIdx.x;
    const int k0 = blockIdx.x * 64;
    const int m0 = blockIdx.y * 32;
#pragma unroll
    for (int i = 0; i < 8; i++) {
        const int idx = tid + i * 256;
        const int r = idx >> 6, cc = idx & 63;
        const int k = k0 + cc;
        s[r][cc] = (k < K) ? A[(size_t)(m0 + r) * K + k] : 0.f;
    }
    __syncthreads();
    const int mblk0 = blockIdx.y * 2, kblk0 = blockIdx.x * 8;
#pragma unroll
    for (int i = 0; i < 2; i++) {
        const int slot = tid + i * 256;       // 0..511
        const int mb = slot >> 8, kb = (slot >> 5) & 7, ln = slot & 31;
        if (kblk0 + kb < KB) {
            const int gg = ln >> 2, cc = ln & 3;
            const int mr = mb * 16 + gg, kc = kb * 8 + cc;
            const float v0 = s[mr][kc],     v1 = s[mr + 8][kc];
            const float v2 = s[mr][kc + 4], v3 = s[mr + 8][kc + 4];
            uint4 h4, l4;
            h4.x = tf32_round(v0); l4.x = tf32_round(v0 - __uint_as_float(h4.x));
            h4.y = tf32_round(v1); l4.y = tf32_round(v1 - __uint_as_float(h4.y));
            h4.z = tf32_round(v2); l4.z = tf32_round(v2 - __uint_as_float(h4.z));
            h4.w = tf32_round(v3); l4.w = tf32_round(v3 - __uint_as_float(h4.w));
            const size_t o = (((size_t)(mblk0 + mb) * KB + kblk0 + kb) * 32 + ln) * 4;
            *(uint4*)&hi[o] = h4;
            *(uint4*)&lo[o] = l4;
        }
    }
}

// ---------------------------------------------------------------------------
// merged split_B for all 4 weights: W[K,N] -> hi/lo B-fragments (pad to NPAD).
// ---------------------------------------------------------------------------
struct SplitBArgs {
    const float* W[4];
    float* hi[4];
    float* lo[4];
    int K[4], N[4], KB[4], gx[4], gy[4];
};

__global__ __launch_bounds__(256) void split_B4_kernel(SplitBArgs a)
{
    const int z = blockIdx.z;
    if ((int)blockIdx.x >= a.gx[z] || (int)blockIdx.y >= a.gy[z]) return;
    const float* __restrict__ W = a.W[z];
    float* __restrict__ hi = a.hi[z];
    float* __restrict__ lo = a.lo[z];
    const int K = a.K[z], N = a.N[z], KB = a.KB[z];

    __shared__ float s[64][33];
    const int tid = threadIdx.x;
    const int n0 = blockIdx.x * 32;
    const int k0 = blockIdx.y * 64;
#pragma unroll
    for (int i = 0; i < 8; i++) {
        const int idx = tid + i * 256;
        const int r = idx >> 5, cc = idx & 31;
        const int k = k0 + r, n = n0 + cc;
        s[r][cc] = (k < K && n < N) ? W[(size_t)k * N + n] : 0.f;
    }
    __syncthreads();
    const int nblk0 = blockIdx.x * 4, kblk0 = blockIdx.y * 8;
#pragma unroll
    for (int i = 0; i < 4; i++) {
        const int slot = tid + i * 256;       // 0..1023
        const int nb = slot >> 8, kb = (slot >> 5) & 7, ln = slot & 31;
        if (kblk0 + kb < KB) {
            const int gg = ln >> 2, cc = ln & 3;
            const float b0 = s[kb * 8 + cc][nb * 8 + gg];
            const float b1 = s[kb * 8 + cc + 4][nb * 8 + gg];
            uint2 h2, l2;
            h2.x = tf32_round(b0); l2.x = tf32_round(b0 - __uint_as_float(h2.x));
            h2.y = tf32_round(b1); l2.y = tf32_round(b1 - __uint_as_float(h2.y));
            const size_t o = (((size_t)(nblk0 + nb) * KB + kblk0 + kb) * 32 + ln) * 2;
            *(uint2*)&hi[o] = h2;
            *(uint2*)&lo[o] = l2;
        }
    }
}

// ---------------------------------------------------------------------------
// 3xTF32 GEMM on pre-split fragments, cp.async double-buffered.
// CTA tile (MBLKS*16) x (NBLKS*8), 256 threads = 8 warps (2M x 4N).
// smem sections sized to the tile: stage = 2*(MBLKS*1KB) + 2*(NBLKS*0.5KB).
// OUTMODE: 0 = normal C, 1 = A-frags of next gemm, 2 = both.
// ---------------------------------------------------------------------------
template <bool RELU, int OUTMODE, int NBLKS, int MBLKS, int OCC>
__global__ __launch_bounds__(256, OCC) void mma_gemm(
    const float* __restrict__ Ahi, const float* __restrict__ Alo,
    const float* __restrict__ Bhi, const float* __restrict__ Blo,
    const float* __restrict__ bias,
    float* __restrict__ Cn, float* __restrict__ Chi, float* __restrict__ Clo,
    int N, int KB, int KBOUT)
{
    constexpr int NTW = NBLKS / 4;    // nblks per warp
    constexpr int MT  = MBLKS / 2;    // mtiles (16 rows each) per warp
    constexpr int A_BYTES = MBLKS * 1024;
    constexpr int B_BYTES = NBLKS * 512;
    constexpr int STAGE   = 2 * A_BYTES + 2 * B_BYTES;

    extern __shared__ char smem[];
    const uint32_t sb32 = smem_u32(smem);
    const int tid = threadIdx.x, wid = tid >> 5, lane = tid & 31;
    const int wm = wid & 1, wn = wid >> 1;
    const int g = lane >> 2, c = lane & 3;
    const int m0 = blockIdx.y * MBLKS * 16, n0 = blockIdx.x * NBLKS * 8;
    const int mblk0 = blockIdx.y * MBLKS, nblk0 = blockIdx.x * NBLKS;

    float acc[MT][NTW][4];
#pragma unroll
    for (int mt = 0; mt < MT; mt++)
#pragma unroll
        for (int nt = 0; nt < NTW; nt++)
#pragma unroll
            for (int i = 0; i < 4; i++) acc[mt][nt][i] = 0.f;

    const int nch = KB >> 1;

    auto issue = [&](int t) {
        const uint32_t s = sb32 + (t & 1) * STAGE;
        const int kb0 = t * 2;
        // A: MBLKS*64 cp16 (MBLKS mblks x 2 kblks x 128 floats)
#pragma unroll
        for (int idx = tid; idx < MBLKS * 64; idx += 256) {
            const int mb = idx >> 6, off = idx & 63;
            const size_t go = ((size_t)(mblk0 + mb) * KB + kb0) * 128 + off * 4;
            cp16(s + idx * 16,           Ahi + go);
            cp16(s + A_BYTES + idx * 16, Alo + go);
        }
        // B: NBLKS*32 cp16 (NBLKS nblks x 2 kblks x 64 floats)
#pragma unroll
        for (int idx = tid; idx < NBLKS * 32; idx += 256) {
            const int nb = idx >> 5, off = idx & 31;
            const size_t go = ((size_t)(nblk0 + nb) * KB + kb0) * 64 + off * 4;
            cp16(s + 2 * A_BYTES + idx * 16,           Bhi + go);
            cp16(s + 2 * A_BYTES + B_BYTES + idx * 16, Blo + go);
        }
    };

    issue(0);
    asm volatile("cp.async.commit_group;");

    for (int t = 0; t < nch; t++) {
        if (t + 1 < nch) {
            issue(t + 1);
            asm volatile("cp.async.commit_group;");
            asm volatile("cp.async.wait_group 1;");
        } else {
            asm volatile("cp.async.wait_group 0;");
        }
        __syncthreads();

        const char* s = smem + (t & 1) * STAGE;
#pragma unroll
        for (int ks = 0; ks < 2; ks++) {
            uint4 ah[MT], al[MT];
#pragma unroll
            for (int mt = 0; mt < MT; mt++) {
                const int off = (((wm * MT + mt) * 2 + ks) * 32 + lane) * 16;
                ah[mt] = *(const uint4*)(s + off);
                al[mt] = *(const uint4*)(s + A_BYTES + off);
            }
            uint2 bh[NTW], bl[NTW];
#pragma unroll
            for (int nt = 0; nt < NTW; nt++) {
                const int off = (((wn * NTW + nt) * 2 + ks) * 32 + lane) * 8;
                bh[nt] = *(const uint2*)(s + 2 * A_BYTES + off);
                bl[nt] = *(const uint2*)(s + 2 * A_BYTES + B_BYTES + off);
            }
#pragma unroll
            for (int mt = 0; mt < MT; mt++)
#pragma unroll
                for (int nt = 0; nt < NTW; nt++) {
                    mma_tf32(acc[mt][nt], (const uint32_t*)&ah[mt], (const uint32_t*)&bh[nt]);
                    mma_tf32(acc[mt][nt], (const uint32_t*)&ah[mt], (const uint32_t*)&bl[nt]);
                    mma_tf32(acc[mt][nt], (const uint32_t*)&al[mt], (const uint32_t*)&bh[nt]);
                }
        }
        __syncthreads();
    }

    // ---- epilogue ----
#pragma unroll
    for (int nt = 0; nt < NTW; nt++) {
        const int col = n0 + (wn * NTW + nt) * 8 + 2 * c;
        if (col < N) {
            const float bx = __ldg(&bias[col]);
            const float by = __ldg(&bias[col + 1]);
#pragma unroll
            for (int mt = 0; mt < MT; mt++) {
                const int row = m0 + (wm * MT + mt) * 16 + g;
                float v00 = acc[mt][nt][0] + bx;
                float v01 = acc[mt][nt][1] + by;
                float v10 = acc[mt][nt][2] + bx;
                float v11 = acc[mt][nt][3] + by;
                if (RELU) {
                    v00 = fmaxf(v00, 0.f); v01 = fmaxf(v01, 0.f);
                    v10 = fmaxf(v10, 0.f); v11 = fmaxf(v11, 0.f);
                }
                if (OUTMODE == 0 || OUTMODE == 2) {
                    *(float2*)&Cn[(size_t)row * N + col]       = make_float2(v00, v01);
                    *(float2*)&Cn[(size_t)(row + 8) * N + col] = make_float2(v10, v11);
                }
                if (OUTMODE == 1 || OUTMODE == 2) {
                    write_frag(v00, row,     col,     KBOUT, Chi, Clo);
                    write_frag(v01, row,     col + 1, KBOUT, Chi, Clo);
                    write_frag(v10, row + 8, col,     KBOUT, Chi, Clo);
                    write_frag(v11, row + 8, col + 1, KBOUT, Chi, Clo);
                }
            }
        }
    }
}

// ---------------------------------------------------------------------------
// Dist v3: dot-product form, reps register-resident (2 clusters/thread).
// d(b,k) = |e_b|^2 + |r_k|^2 - 2 e_b.r_k
// Block = 256 threads, 64 rows, 8 row-groups of 8; shuffle + smem reductions.
// ---------------------------------------------------------------------------
__global__ __launch_bounds__(256) void dist_softmin_kernel(
    const float* __restrict__ emb, const float* __restrict__ reps,
    float* __restrict__ weighted, float* __restrict__ distances)
{
    __shared__ float emb_s[64 * NE];     // 8KB
    __shared__ float en_s[64];
    __shared__ float red_s[8 * 8];       // [warp][row-in-group]
    __shared__ float rmin_s[8], rsum_s[8];

    const int tid  = threadIdx.x;
    const int wid  = tid >> 5;
    const int lane = tid & 31;
    const int brow = blockIdx.x * 64;
    const int c0   = tid * 2;

    // load 2 cluster reps into registers + norms
    float r0[NE], r1[NE];
    float rn0 = 0.f, rn1 = 0.f;
    const float4* rp0 = (const float4*)(reps + (size_t)c0 * NE);
    const float4* rp1 = (const float4*)(reps + (size_t)(c0 + 1) * NE);
#pragma unroll
    for (int e4 = 0; e4 < 8; e4++) {
        float4 a = rp0[e4], b = rp1[e4];
        r0[e4*4+0] = a.x; r0[e4*4+1] = a.y; r0[e4*4+2] = a.z; r0[e4*4+3] = a.w;
        r1[e4*4+0] = b.x; r1[e4*4+1] = b.y; r1[e4*4+2] = b.z; r1[e4*4+3] = b.w;
        rn0 = fmaf(a.x, a.x, rn0); rn0 = fmaf(a.y, a.y, rn0);
        rn0 = fmaf(a.z, a.z, rn0); rn0 = fmaf(a.w, a.w, rn0);
        rn1 = fmaf(b.x, b.x, rn1); rn1 = fmaf(b.y, b.y, rn1);
        rn1 = fmaf(b.z, b.z, rn1); rn1 = fmaf(b.w, b.w, rn1);
    }

    // stage 64 emb rows
    const float4* embg = (const float4*)(emb + (size_t)brow * NE);
    for (int idx = tid; idx < 64 * NE / 4; idx += 256)
        ((float4*)emb_s)[idx] = embg[idx];
    __syncthreads();
    // row norms
    if (tid < 64) {
        const float4* ep = (const float4*)(emb_s + tid * NE);
        float s = 0.f;
#pragma unroll
        for (int e4 = 0; e4 < 8; e4++) {
            float4 v = ep[e4];
            s = fmaf(v.x, v.x, s); s = fmaf(v.y, v.y, s);
            s = fmaf(v.z, v.z, s); s = fmaf(v.w, v.w, s);
        }
        en_s[tid] = s;
    }
    __syncthreads();

#pragma unroll 1
    for (int gq = 0; gq < 8; gq++) {
        float d0[8], d1[8];
#pragma unroll
        for (int i = 0; i < 8; i++) {
            const int r = gq * 8 + i;
            const float4* ep = (const float4*)(emb_s + r * NE);
            float dot0 = 0.f, dot1 = 0.f;
#pragma unroll
            for (int e4 = 0; e4 < 8; e4++) {
                float4 ev = ep[e4];   // broadcast LDS.128
                dot0 = fmaf(ev.x, r0[e4*4+0], dot0);
                dot0 = fmaf(ev.y, r0[e4*4+1], dot0);
                dot0 = fmaf(ev.z, r0[e4*4+2], dot0);
                dot0 = fmaf(ev.w, r0[e4*4+3], dot0);
                dot1 = fmaf(ev.x, r1[e4*4+0], dot1);
                dot1 = fmaf(ev.y, r1[e4*4+1], dot1);
                dot1 = fmaf(ev.z, r1[e4*4+2], dot1);
                dot1 = fmaf(ev.w, r1[e4*4+3], dot1);
            }
            const float en = en_s[r];
            d0[i] = fmaf(-2.f, dot0, en + rn0);
            d1[i] = fmaf(-2.f, dot1, en + rn1);
        }

        // block-wide min per row
#pragma unroll
        for (int i = 0; i < 8; i++) {
            float v = fminf(d0[i], d1[i]);
#pragma unroll
            for (int o = 16; o > 0; o >>= 1)
                v = fminf(v, __shfl_xor_sync(0xFFFFFFFF, v, o));
            if (lane == 0) red_s[wid * 8 + i] = v;
        }
        __syncthreads();
        if (tid < 8) {
            float m = red_s[tid];
#pragma unroll
            for (int w = 1; w < 8; w++) m = fminf(m, red_s[w * 8 + tid]);
            rmin_s[tid] = m;
        }
        __syncthreads();

        // block-wide exp-sum per row
#pragma unroll
        for (int i = 0; i < 8; i++) {
            const float mv = rmin_s[i];
            float ps = expf(-ALPHA * (d0[i] - mv)) + expf(-ALPHA * (d1[i] - mv));
#pragma unroll
            for (int o = 16; o > 0; o >>= 1)
                ps += __shfl_xor_sync(0xFFFFFFFF, ps, o);
            if (lane == 0) red_s[wid * 8 + i] = ps;
        }
        __syncthreads();
        if (tid < 8) {
            float s = red_s[tid];
#pragma unroll
            for (int w = 1; w < 8; w++) s += red_s[w * 8 + tid];
            rsum_s[tid] = s;
        }
        __syncthreads();

        // stores (float2, coalesced)
#pragma unroll
        for (int i = 0; i < 8; i++) {
            const float mv  = rmin_s[i];
            const float inv = 1.0f / rsum_s[i];
            const float dv0 = d0[i], dv1 = d1[i];
            const size_t base = (size_t)(brow + gq * 8 + i) * NK + c0;
            *(float2*)&distances[base] = make_float2(dv0, dv1);
            *(float2*)&weighted[base]  = make_float2(
                dv0 * expf(-ALPHA * (dv0 - mv)) * inv,
                dv1 * expf(-ALPHA * (dv1 - mv)) * inv);
        }
        __syncthreads();   // protect rmin_s/rsum_s/red_s before next group
    }
}

// ---------------------------------------------------------------------------
extern "C" void kernel_launch(void* const* d_in, const int* in_sizes, int n_in,
                              void* d_out, int out_size)
{
    const float* x    = (const float*)d_in[0];
    const float* reps = (const float*)d_in[1];
    const float* W1   = (const float*)d_in[2];
    const float* b1   = (const float*)d_in[3];
    const float* W2   = (const float*)d_in[4];
    const float* b2   = (const float*)d_in[5];
    const float* W3   = (const float*)d_in[6];
    const float* b3   = (const float*)d_in[7];
    const float* W4   = (const float*)d_in[8];
    const float* b4   = (const float*)d_in[9];

    float* out       = (float*)d_out;
    float* weighted  = out;
    float* distances = out + (size_t)NB * NK;
    float* rec       = out + 2 * (size_t)NB * NK;
    float* emb       = out + 2 * (size_t)NB * NK + (size_t)NB * ND;

    float *xhi, *xlo, *hhi, *hlo, *ehi, *elo, *h2hi, *h2lo;
    float *w1hi, *w1lo, *w2hi, *w2lo, *w3hi, *w3lo, *w4hi, *w4lo;
    cudaGetSymbolAddress((void**)&xhi,  g_xhi);  cudaGetSymbolAddress((void**)&xlo,  g_xlo);
    cudaGetSymbolAddress((void**)&hhi,  g_hhi);  cudaGetSymbolAddress((void**)&hlo,  g_hlo);
    cudaGetSymbolAddress((void**)&ehi,  g_ehi);  cudaGetSymbolAddress((void**)&elo,  g_elo);
    cudaGetSymbolAddress((void**)&h2hi, g_h2hi); cudaGetSymbolAddress((void**)&h2lo, g_h2lo);
    cudaGetSymbolAddress((void**)&w1hi, g_w1hi); cudaGetSymbolAddress((void**)&w1lo, g_w1lo);
    cudaGetSymbolAddress((void**)&w2hi, g_w2hi); cudaGetSymbolAddress((void**)&w2lo, g_w2lo);
    cudaGetSymbolAddress((void**)&w3hi, g_w3hi); cudaGetSymbolAddress((void**)&w3lo, g_w3lo);
    cudaGetSymbolAddress((void**)&w4hi, g_w4hi); cudaGetSymbolAddress((void**)&w4lo, g_w4lo);

    // smem sizes: 2 stages * (2*MBLKS*1024 + 2*NBLKS*512)
    const int smem_g1 = 2 * (2 * 8 * 1024 + 2 * 8 * 512);    // 49152
    const int smem_g2 = 2 * (2 * 4 * 1024 + 2 * 4 * 512);    // 24576
    const int smem_g4 = 2 * (2 * 8 * 1024 + 2 * 16 * 512);   // 65536
    cudaFuncSetAttribute((const void*)mma_gemm<true, 1, 8, 8, 2>,
                         cudaFuncAttributeMaxDynamicSharedMemorySize, smem_g1);
    cudaFuncSetAttribute((const void*)mma_gemm<false, 2, 4, 4, 3>,
                         cudaFuncAttributeMaxDynamicSharedMemorySize, smem_g2);
    cudaFuncSetAttribute((const void*)mma_gemm<false, 0, 16, 8, 2>,
                         cudaFuncAttributeMaxDynamicSharedMemorySize, smem_g4);

    // ---- operand pre-splits ----
    split_A_kernel<<<dim3(13, NB / 32), 256>>>(x, xhi, xlo, ND, 98);
    {
        SplitBArgs a;
        a.W[0] = W1;   a.hi[0] = w1hi; a.lo[0] = w1lo;
        a.K[0] = ND;   a.N[0] = NH;    a.KB[0] = 98; a.gx[0] = 8;  a.gy[0] = 13;
        a.W[1] = W2;   a.hi[1] = w2hi; a.lo[1] = w2lo;
        a.K[1] = NH;   a.N[1] = NE;    a.KB[1] = 32; a.gx[1] = 1;  a.gy[1] = 4;
        a.W[2] = W3;   a.hi[2] = w3hi; a.lo[2] = w3lo;
        a.K[2] = NE;   a.N[2] = NH;    a.KB[2] = 4;  a.gx[2] = 8;  a.gy[2] = 1;
        a.W[3] = W4;   a.hi[3] = w4hi; a.lo[3] = w4lo;
        a.K[3] = NH;   a.N[3] = ND;    a.KB[3] = 32; a.gx[3] = 28; a.gy[3] = 4;
        split_B4_kernel<<<dim3(28, 13, 4), 256>>>(a);
    }

    // ---- GEMM chain ----
    // h = relu(x @ W1 + b1)  -> h fragments          (128x64 tiles, 256 CTAs)
    mma_gemm<true, 1, 8, 8, 2><<<dim3(4, NB / 128), 256, smem_g1>>>(
        xhi, xlo, w1hi, w1lo, b1, nullptr, hhi, hlo, NH, 98, 32);
    // emb = h @ W2 + b2      -> normal emb + emb fragments (64x32 tiles, 128 CTAs)
    mma_gemm<false, 2, 4, 4, 3><<<dim3(1, NB / 64), 256, smem_g2>>>(
        hhi, hlo, w2hi, w2lo, b2, emb, ehi, elo, NE, 32, 4);
    // h2 = relu(emb @ W3 + b3) -> h2 fragments       (128x64 tiles, 256 CTAs)
    mma_gemm<true, 1, 8, 8, 2><<<dim3(4, NB / 128), 256, smem_g1>>>(
        ehi, elo, w3hi, w3lo, b3, nullptr, h2hi, h2lo, NH, 4, 32);
    // rec = h2 @ W4 + b4     -> normal output        (128x128 tiles, 448 CTAs)
    mma_gemm<false, 0, 16, 8, 2><<<dim3(7, NB / 128), 256, smem_g4>>>(
        h2hi, h2lo, w4hi, w4lo, b4, rec, nullptr, nullptr, ND, 32, 0);

    // ---- distances + softmin ----
    dist_softmin_kernel<<<NB / 64, 256>>>(emb, reps, weighted, distances);
}

// round 12
// speedup vs baseline: 1.2194x; 1.0110x over previous
#include <cuda_runtime.h>
#include <cstdint>
#include <math.h>

#define ALPHA 1000.0f
#define NB 8192
#define ND 784
#define NH 256
#define NE 32
#define NK 512

// ---------------------------------------------------------------------------
// Fragment-major hi/lo scratch (allocation-free rule: __device__ globals).
// A-frag layout: [mblk][KB][32 lanes][4]  (128 floats / block)
// B-frag layout: [nblk][KB][32 lanes][2]  (64 floats / block)
// ---------------------------------------------------------------------------
__device__ float g_xhi [NB * ND], g_xlo [NB * ND];     // x    A-frags, KB=98
__device__ float g_hhi [NB * NH], g_hlo [NB * NH];     // h    A-frags, KB=32
__device__ float g_ehi [NB * NE], g_elo [NB * NE];     // emb  A-frags, KB=4
__device__ float g_h2hi[NB * NH], g_h2lo[NB * NH];     // h2   A-frags, KB=32
__device__ float g_w1hi[32 * 98 * 64],  g_w1lo[32 * 98 * 64];    // W1 (N=256)
__device__ float g_w2hi[4 * 32 * 64],   g_w2lo[4 * 32 * 64];     // W2 (NPAD=32)
__device__ float g_w3hi[32 * 4 * 64],   g_w3lo[32 * 4 * 64];     // W3 (N=256)
__device__ float g_w4hi[112 * 32 * 64], g_w4lo[112 * 32 * 64];   // W4 (NPAD=896)

// ---------------------------------------------------------------------------
// helpers (baseline PTX only)
// ---------------------------------------------------------------------------
__device__ __forceinline__ uint32_t tf32_round(float x) {
    uint32_t u;
    asm("cvt.rna.tf32.f32 %0, %1;" : "=r"(u) : "f"(x));
    return u;
}
__device__ __forceinline__ void mma_tf32(float* d, const uint32_t* a, const uint32_t* b) {
    asm volatile(
        "mma.sync.aligned.m16n8k8.row.col.f32.tf32.tf32.f32 "
        "{%0,%1,%2,%3}, {%4,%5,%6,%7}, {%8,%9}, {%0,%1,%2,%3};"
        : "+f"(d[0]), "+f"(d[1]), "+f"(d[2]), "+f"(d[3])
        : "r"(a[0]), "r"(a[1]), "r"(a[2]), "r"(a[3]), "r"(b[0]), "r"(b[1]));
}
__device__ __forceinline__ uint32_t smem_u32(const void* p) {
    uint32_t a;
    asm("{ .reg .u64 t; cvta.to.shared.u64 t, %1; cvt.u32.u64 %0, t; }" : "=r"(a) : "l"(p));
    return a;
}
__device__ __forceinline__ void cp16(uint32_t dst, const void* src) {
    asm volatile("cp.async.cg.shared.global [%0], [%1], 16;" :: "r"(dst), "l"(src));
}

// write one value into A-fragment hi/lo buffers (for the next GEMM)
__device__ __forceinline__ void write_frag(float v, int m, int k, int KB,
                                           float* ghi, float* glo) {
    uint32_t hi = tf32_round(v);
    uint32_t lo = tf32_round(v - __uint_as_float(hi));
    const int mblk = m >> 4, kblk = k >> 3;
    const int ln   = ((m & 7) << 2) | (k & 3);
    const int slot = ((m >> 3) & 1) | (((k >> 2) & 1) << 1);
    const size_t o = (((size_t)mblk * KB + kblk) * 32 + ln) * 4 + slot;
    ((uint32_t*)ghi)[o] = hi;
    ((uint32_t*)glo)[o] = lo;
}

// ---------------------------------------------------------------------------
// split_A: A[M,K] row-major -> hi/lo A-fragments. Tile 32m x 64k per block.
// ---------------------------------------------------------------------------
__global__ __launch_bounds__(256) void split_A_kernel(
    const float* __restrict__ A, float* __restrict__ hi, float* __restrict__ lo,
    int K, int KB)
{
    __shared__ float s[32][65];
    const int tid = threadIdx.x;
    const int k0 = blockIdx.x * 64;
    const int m0 = blockIdx.y * 32;
#pragma unroll
    for (int i = 0; i < 8; i++) {
        const int idx = tid + i * 256;
        const int r = idx >> 6, cc = idx & 63;
        const int k = k0 + cc;
        s[r][cc] = (k < K) ? A[(size_t)(m0 + r) * K + k] : 0.f;
    }
    __syncthreads();
    const int mblk0 = blockIdx.y * 2, kblk0 = blockIdx.x * 8;
#pragma unroll
    for (int i = 0; i < 2; i++) {
        const int slot = tid + i * 256;       // 0..511
        const int mb = slot >> 8, kb = (slot >> 5) & 7, ln = slot & 31;
        if (kblk0 + kb < KB) {
            const int gg = ln >> 2, cc = ln & 3;
            const int mr = mb * 16 + gg, kc = kb * 8 + cc;
            const float v0 = s[mr][kc],     v1 = s[mr + 8][kc];
            const float v2 = s[mr][kc + 4], v3 = s[mr + 8][kc + 4];
            uint4 h4, l4;
            h4.x = tf32_round(v0); l4.x = tf32_round(v0 - __uint_as_float(h4.x));
            h4.y = tf32_round(v1); l4.y = tf32_round(v1 - __uint_as_float(h4.y));
            h4.z = tf32_round(v2); l4.z = tf32_round(v2 - __uint_as_float(h4.z));
            h4.w = tf32_round(v3); l4.w = tf32_round(v3 - __uint_as_float(h4.w));
            const size_t o = (((size_t)(mblk0 + mb) * KB + kblk0 + kb) * 32 + ln) * 4;
            *(uint4*)&hi[o] = h4;
            *(uint4*)&lo[o] = l4;
        }
    }
}

// ---------------------------------------------------------------------------
// merged split_B for all 4 weights: W[K,N] -> hi/lo B-fragments (pad to NPAD).
// ---------------------------------------------------------------------------
struct SplitBArgs {
    const float* W[4];
    float* hi[4];
    float* lo[4];
    int K[4], N[4], KB[4], gx[4], gy[4];
};

__global__ __launch_bounds__(256) void split_B4_kernel(SplitBArgs a)
{
    const int z = blockIdx.z;
    if ((int)blockIdx.x >= a.gx[z] || (int)blockIdx.y >= a.gy[z]) return;
    const float* __restrict__ W = a.W[z];
    float* __restrict__ hi = a.hi[z];
    float* __restrict__ lo = a.lo[z];
    const int K = a.K[z], N = a.N[z], KB = a.KB[z];

    __shared__ float s[64][33];
    const int tid = threadIdx.x;
    const int n0 = blockIdx.x * 32;
    const int k0 = blockIdx.y * 64;
#pragma unroll
    for (int i = 0; i < 8; i++) {
        const int idx = tid + i * 256;
        const int r = idx >> 5, cc = idx & 31;
        const int k = k0 + r, n = n0 + cc;
        s[r][cc] = (k < K && n < N) ? W[(size_t)k * N + n] : 0.f;
    }
    __syncthreads();
    const int nblk0 = blockIdx.x * 4, kblk0 = blockIdx.y * 8;
#pragma unroll
    for (int i = 0; i < 4; i++) {
        const int slot = tid + i * 256;       // 0..1023
        const int nb = slot >> 8, kb = (slot >> 5) & 7, ln = slot & 31;
        if (kblk0 + kb < KB) {
            const int gg = ln >> 2, cc = ln & 3;
            const float b0 = s[kb * 8 + cc][nb * 8 + gg];
            const float b1 = s[kb * 8 + cc + 4][nb * 8 + gg];
            uint2 h2, l2;
            h2.x = tf32_round(b0); l2.x = tf32_round(b0 - __uint_as_float(h2.x));
            h2.y = tf32_round(b1); l2.y = tf32_round(b1 - __uint_as_float(h2.y));
            const size_t o = (((size_t)(nblk0 + nb) * KB + kblk0 + kb) * 32 + ln) * 2;
            *(uint2*)&hi[o] = h2;
            *(uint2*)&lo[o] = l2;
        }
    }
}

// ---------------------------------------------------------------------------
// 3xTF32 GEMM on pre-split fragments, 3-stage cp.async pipeline.
// CTA tile (MBLKS*16) x (NBLKS*8), 256 threads = 8 warps (2M x 4N).
// smem: 3 stages x (2*MBLKS*1KB + 2*NBLKS*0.5KB).
// OUTMODE: 0 = normal C, 1 = A-frags of next gemm, 2 = both.
// ---------------------------------------------------------------------------
template <bool RELU, int OUTMODE, int NBLKS, int MBLKS, int OCC>
__global__ __launch_bounds__(256, OCC) void mma_gemm(
    const float* __restrict__ Ahi, const float* __restrict__ Alo,
    const float* __restrict__ Bhi, const float* __restrict__ Blo,
    const float* __restrict__ bias,
    float* __restrict__ Cn, float* __restrict__ Chi, float* __restrict__ Clo,
    int N, int KB, int KBOUT)
{
    constexpr int NTW = NBLKS / 4;    // nblks per warp
    constexpr int MT  = MBLKS / 2;    // mtiles (16 rows each) per warp
    constexpr int A_BYTES = MBLKS * 1024;
    constexpr int B_BYTES = NBLKS * 512;
    constexpr int STAGE   = 2 * A_BYTES + 2 * B_BYTES;

    extern __shared__ char smem[];
    const uint32_t sb32 = smem_u32(smem);
    const int tid = threadIdx.x, wid = tid >> 5, lane = tid & 31;
    const int wm = wid & 1, wn = wid >> 1;
    const int g = lane >> 2, c = lane & 3;
    const int m0 = blockIdx.y * MBLKS * 16, n0 = blockIdx.x * NBLKS * 8;
    const int mblk0 = blockIdx.y * MBLKS, nblk0 = blockIdx.x * NBLKS;

    float acc[MT][NTW][4];
#pragma unroll
    for (int mt = 0; mt < MT; mt++)
#pragma unroll
        for (int nt = 0; nt < NTW; nt++)
#pragma unroll
            for (int i = 0; i < 4; i++) acc[mt][nt][i] = 0.f;

    const int nch = KB >> 1;

    auto issue = [&](int t) {
        const uint32_t s = sb32 + (t % 3) * STAGE;
        const int kb0 = t * 2;
        // A: MBLKS*64 cp16 (MBLKS mblks x 2 kblks x 128 floats)
#pragma unroll
        for (int idx = tid; idx < MBLKS * 64; idx += 256) {
            const int mb = idx >> 6, off = idx & 63;
            const size_t go = ((size_t)(mblk0 + mb) * KB + kb0) * 128 + off * 4;
            cp16(s + idx * 16,           Ahi + go);
            cp16(s + A_BYTES + idx * 16, Alo + go);
        }
        // B: NBLKS*32 cp16 (NBLKS nblks x 2 kblks x 64 floats)
#pragma unroll
        for (int idx = tid; idx < NBLKS * 32; idx += 256) {
            const int nb = idx >> 5, off = idx & 31;
            const size_t go = ((size_t)(nblk0 + nb) * KB + kb0) * 64 + off * 4;
            cp16(s + 2 * A_BYTES + idx * 16,           Bhi + go);
            cp16(s + 2 * A_BYTES + B_BYTES + idx * 16, Blo + go);
        }
    };

    int issued = 0;
    const int pre = (nch < 2) ? nch : 2;
    for (; issued < pre; issued++) {
        issue(issued);
        asm volatile("cp.async.commit_group;");
    }

    for (int t = 0; t < nch; t++) {
        if (issued < nch) {
            issue(issued);
            asm volatile("cp.async.commit_group;");
            issued++;
        }
        const int pending = issued - t - 1;
        if (pending >= 2)      asm volatile("cp.async.wait_group 2;");
        else if (pending == 1) asm volatile("cp.async.wait_group 1;");
        else                   asm volatile("cp.async.wait_group 0;");
        __syncthreads();

        const char* s = smem + (t % 3) * STAGE;
#pragma unroll
        for (int ks = 0; ks < 2; ks++) {
            uint4 ah[MT], al[MT];
#pragma unroll
            for (int mt = 0; mt < MT; mt++) {
                const int off = (((wm * MT + mt) * 2 + ks) * 32 + lane) * 16;
                ah[mt] = *(const uint4*)(s + off);
                al[mt] = *(const uint4*)(s + A_BYTES + off);
            }
            uint2 bh[NTW], bl[NTW];
#pragma unroll
            for (int nt = 0; nt < NTW; nt++) {
                const int off = (((wn * NTW + nt) * 2 + ks) * 32 + lane) * 8;
                bh[nt] = *(const uint2*)(s + 2 * A_BYTES + off);
                bl[nt] = *(const uint2*)(s + 2 * A_BYTES + B_BYTES + off);
            }
#pragma unroll
            for (int mt = 0; mt < MT; mt++)
#pragma unroll
                for (int nt = 0; nt < NTW; nt++) {
                    mma_tf32(acc[mt][nt], (const uint32_t*)&ah[mt], (const uint32_t*)&bh[nt]);
                    mma_tf32(acc[mt][nt], (const uint32_t*)&ah[mt], (const uint32_t*)&bl[nt]);
                    mma_tf32(acc[mt][nt], (const uint32_t*)&al[mt], (const uint32_t*)&bh[nt]);
                }
        }
        __syncthreads();
    }

    // ---- epilogue ----
#pragma unroll
    for (int nt = 0; nt < NTW; nt++) {
        const int col = n0 + (wn * NTW + nt) * 8 + 2 * c;
        if (col < N) {
            const float bx = __ldg(&bias[col]);
            const float by = __ldg(&bias[col + 1]);
#pragma unroll
            for (int mt = 0; mt < MT; mt++) {
                const int row = m0 + (wm * MT + mt) * 16 + g;
                float v00 = acc[mt][nt][0] + bx;
                float v01 = acc[mt][nt][1] + by;
                float v10 = acc[mt][nt][2] + bx;
                float v11 = acc[mt][nt][3] + by;
                if (RELU) {
                    v00 = fmaxf(v00, 0.f); v01 = fmaxf(v01, 0.f);
                    v10 = fmaxf(v10, 0.f); v11 = fmaxf(v11, 0.f);
                }
                if (OUTMODE == 0 || OUTMODE == 2) {
                    *(float2*)&Cn[(size_t)row * N + col]       = make_float2(v00, v01);
                    *(float2*)&Cn[(size_t)(row + 8) * N + col] = make_float2(v10, v11);
                }
                if (OUTMODE == 1 || OUTMODE == 2) {
                    write_frag(v00, row,     col,     KBOUT, Chi, Clo);
                    write_frag(v01, row,     col + 1, KBOUT, Chi, Clo);
                    write_frag(v10, row + 8, col,     KBOUT, Chi, Clo);
                    write_frag(v11, row + 8, col + 1, KBOUT, Chi, Clo);
                }
            }
        }
    }
}

// ---------------------------------------------------------------------------
// Dist v3: dot-product form, reps register-resident (2 clusters/thread).
// d(b,k) = |e_b|^2 + |r_k|^2 - 2 e_b.r_k
// Block = 256 threads, 64 rows, 8 row-groups of 8; shuffle + smem reductions.
// ---------------------------------------------------------------------------
__global__ __launch_bounds__(256) void dist_softmin_kernel(
    const float* __restrict__ emb, const float* __restrict__ reps,
    float* __restrict__ weighted, float* __restrict__ distances)
{
    __shared__ float emb_s[64 * NE];     // 8KB
    __shared__ float en_s[64];
    __shared__ float red_s[8 * 8];       // [warp][row-in-group]
    __shared__ float rmin_s[8], rsum_s[8];

    const int tid  = threadIdx.x;
    const int wid  = tid >> 5;
    const int lane = tid & 31;
    const int brow = blockIdx.x * 64;
    const int c0   = tid * 2;

    // load 2 cluster reps into registers + norms
    float r0[NE], r1[NE];
    float rn0 = 0.f, rn1 = 0.f;
    const float4* rp0 = (const float4*)(reps + (size_t)c0 * NE);
    const float4* rp1 = (const float4*)(reps + (size_t)(c0 + 1) * NE);
#pragma unroll
    for (int e4 = 0; e4 < 8; e4++) {
        float4 a = rp0[e4], b = rp1[e4];
        r0[e4*4+0] = a.x; r0[e4*4+1] = a.y; r0[e4*4+2] = a.z; r0[e4*4+3] = a.w;
        r1[e4*4+0] = b.x; r1[e4*4+1] = b.y; r1[e4*4+2] = b.z; r1[e4*4+3] = b.w;
        rn0 = fmaf(a.x, a.x, rn0); rn0 = fmaf(a.y, a.y, rn0);
        rn0 = fmaf(a.z, a.z, rn0); rn0 = fmaf(a.w, a.w, rn0);
        rn1 = fmaf(b.x, b.x, rn1); rn1 = fmaf(b.y, b.y, rn1);
        rn1 = fmaf(b.z, b.z, rn1); rn1 = fmaf(b.w, b.w, rn1);
    }

    // stage 64 emb rows
    const float4* embg = (const float4*)(emb + (size_t)brow * NE);
    for (int idx = tid; idx < 64 * NE / 4; idx += 256)
        ((float4*)emb_s)[idx] = embg[idx];
    __syncthreads();
    // row norms
    if (tid < 64) {
        const float4* ep = (const float4*)(emb_s + tid * NE);
        float s = 0.f;
#pragma unroll
        for (int e4 = 0; e4 < 8; e4++) {
            float4 v = ep[e4];
            s = fmaf(v.x, v.x, s); s = fmaf(v.y, v.y, s);
            s = fmaf(v.z, v.z, s); s = fmaf(v.w, v.w, s);
        }
        en_s[tid] = s;
    }
    __syncthreads();

#pragma unroll 1
    for (int gq = 0; gq < 8; gq++) {
        float d0[8], d1[8];
#pragma unroll
        for (int i = 0; i < 8; i++) {
            const int r = gq * 8 + i;
            const float4* ep = (const float4*)(emb_s + r * NE);
            float dot0 = 0.f, dot1 = 0.f;
#pragma unroll
            for (int e4 = 0; e4 < 8; e4++) {
                float4 ev = ep[e4];   // broadcast LDS.128
                dot0 = fmaf(ev.x, r0[e4*4+0], dot0);
                dot0 = fmaf(ev.y, r0[e4*4+1], dot0);
                dot0 = fmaf(ev.z, r0[e4*4+2], dot0);
                dot0 = fmaf(ev.w, r0[e4*4+3], dot0);
                dot1 = fmaf(ev.x, r1[e4*4+0], dot1);
                dot1 = fmaf(ev.y, r1[e4*4+1], dot1);
                dot1 = fmaf(ev.z, r1[e4*4+2], dot1);
                dot1 = fmaf(ev.w, r1[e4*4+3], dot1);
            }
            const float en = en_s[r];
            d0[i] = fmaf(-2.f, dot0, en + rn0);
            d1[i] = fmaf(-2.f, dot1, en + rn1);
        }

        // block-wide min per row
#pragma unroll
        for (int i = 0; i < 8; i++) {
            float v = fminf(d0[i], d1[i]);
#pragma unroll
            for (int o = 16; o > 0; o >>= 1)
                v = fminf(v, __shfl_xor_sync(0xFFFFFFFF, v, o));
            if (lane == 0) red_s[wid * 8 + i] = v;
        }
        __syncthreads();
        if (tid < 8) {
            float m = red_s[tid];
#pragma unroll
            for (int w = 1; w < 8; w++) m = fminf(m, red_s[w * 8 + tid]);
            rmin_s[tid] = m;
        }
        __syncthreads();

        // block-wide exp-sum per row
#pragma unroll
        for (int i = 0; i < 8; i++) {
            const float mv = rmin_s[i];
            float ps = expf(-ALPHA * (d0[i] - mv)) + expf(-ALPHA * (d1[i] - mv));
#pragma unroll
            for (int o = 16; o > 0; o >>= 1)
                ps += __shfl_xor_sync(0xFFFFFFFF, ps, o);
            if (lane == 0) red_s[wid * 8 + i] = ps;
        }
        __syncthreads();
        if (tid < 8) {
            float s = red_s[tid];
#pragma unroll
            for (int w = 1; w < 8; w++) s += red_s[w * 8 + tid];
            rsum_s[tid] = s;
        }
        __syncthreads();

        // stores (float2, coalesced)
#pragma unroll
        for (int i = 0; i < 8; i++) {
            const float mv  = rmin_s[i];
            const float inv = 1.0f / rsum_s[i];
            const float dv0 = d0[i], dv1 = d1[i];
            const size_t base = (size_t)(brow + gq * 8 + i) * NK + c0;
            *(float2*)&distances[base] = make_float2(dv0, dv1);
            *(float2*)&weighted[base]  = make_float2(
                dv0 * expf(-ALPHA * (dv0 - mv)) * inv,
                dv1 * expf(-ALPHA * (dv1 - mv)) * inv);
        }
        __syncthreads();   // protect rmin_s/rsum_s/red_s before next group
    }
}

// ---------------------------------------------------------------------------
extern "C" void kernel_launch(void* const* d_in, const int* in_sizes, int n_in,
                              void* d_out, int out_size)
{
    const float* x    = (const float*)d_in[0];
    const float* reps = (const float*)d_in[1];
    const float* W1   = (const float*)d_in[2];
    const float* b1   = (const float*)d_in[3];
    const float* W2   = (const float*)d_in[4];
    const float* b2   = (const float*)d_in[5];
    const float* W3   = (const float*)d_in[6];
    const float* b3   = (const float*)d_in[7];
    const float* W4   = (const float*)d_in[8];
    const float* b4   = (const float*)d_in[9];

    float* out       = (float*)d_out;
    float* weighted  = out;
    float* distances = out + (size_t)NB * NK;
    float* rec       = out + 2 * (size_t)NB * NK;
    float* emb       = out + 2 * (size_t)NB * NK + (size_t)NB * ND;

    float *xhi, *xlo, *hhi, *hlo, *ehi, *elo, *h2hi, *h2lo;
    float *w1hi, *w1lo, *w2hi, *w2lo, *w3hi, *w3lo, *w4hi, *w4lo;
    cudaGetSymbolAddress((void**)&xhi,  g_xhi);  cudaGetSymbolAddress((void**)&xlo,  g_xlo);
    cudaGetSymbolAddress((void**)&hhi,  g_hhi);  cudaGetSymbolAddress((void**)&hlo,  g_hlo);
    cudaGetSymbolAddress((void**)&ehi,  g_ehi);  cudaGetSymbolAddress((void**)&elo,  g_elo);
    cudaGetSymbolAddress((void**)&h2hi, g_h2hi); cudaGetSymbolAddress((void**)&h2lo, g_h2lo);
    cudaGetSymbolAddress((void**)&w1hi, g_w1hi); cudaGetSymbolAddress((void**)&w1lo, g_w1lo);
    cudaGetSymbolAddress((void**)&w2hi, g_w2hi); cudaGetSymbolAddress((void**)&w2lo, g_w2lo);
    cudaGetSymbolAddress((void**)&w3hi, g_w3hi); cudaGetSymbolAddress((void**)&w3lo, g_w3lo);
    cudaGetSymbolAddress((void**)&w4hi, g_w4hi); cudaGetSymbolAddress((void**)&w4lo, g_w4lo);

    // smem sizes: 3 stages * (2*MBLKS*1024 + 2*NBLKS*512)
    const int smem_g1 = 3 * (2 * 8 * 1024 + 2 * 8 * 512);    // 73728
    const int smem_g2 = 3 * (2 * 2 * 1024 + 2 * 4 * 512);    // 24576
    const int smem_g4 = 3 * (2 * 8 * 1024 + 2 * 16 * 512);   // 98304
    cudaFuncSetAttribute((const void*)mma_gemm<true, 1, 8, 8, 2>,
                         cudaFuncAttributeMaxDynamicSharedMemorySize, smem_g1);
    cudaFuncSetAttribute((const void*)mma_gemm<false, 2, 4, 2, 4>,
                         cudaFuncAttributeMaxDynamicSharedMemorySize, smem_g2);
    cudaFuncSetAttribute((const void*)mma_gemm<false, 0, 16, 8, 2>,
                         cudaFuncAttributeMaxDynamicSharedMemorySize, smem_g4);

    // ---- operand pre-splits ----
    split_A_kernel<<<dim3(13, NB / 32), 256>>>(x, xhi, xlo, ND, 98);
    {
        SplitBArgs a;
        a.W[0] = W1;   a.hi[0] = w1hi; a.lo[0] = w1lo;
        a.K[0] = ND;   a.N[0] = NH;    a.KB[0] = 98; a.gx[0] = 8;  a.gy[0] = 13;
        a.W[1] = W2;   a.hi[1] = w2hi; a.lo[1] = w2lo;
        a.K[1] = NH;   a.N[1] = NE;    a.KB[1] = 32; a.gx[1] = 1;  a.gy[1] = 4;
        a.W[2] = W3;   a.hi[2] = w3hi; a.lo[2] = w3lo;
        a.K[2] = NE;   a.N[2] = NH;    a.KB[2] = 4;  a.gx[2] = 8;  a.gy[2] = 1;
        a.W[3] = W4;   a.hi[3] = w4hi; a.lo[3] = w4lo;
        a.K[3] = NH;   a.N[3] = ND;    a.KB[3] = 32; a.gx[3] = 28; a.gy[3] = 4;
        split_B4_kernel<<<dim3(28, 13, 4), 256>>>(a);
    }

    // ---- GEMM chain ----
    // h = relu(x @ W1 + b1)  -> h fragments          (128x64 tiles, 256 CTAs)
    mma_gemm<true, 1, 8, 8, 2><<<dim3(4, NB / 128), 256, smem_g1>>>(
        xhi, xlo, w1hi, w1lo, b1, nullptr, hhi, hlo, NH, 98, 32);
    // emb = h @ W2 + b2      -> normal emb + emb fragments (32x32 tiles, 256 CTAs)
    mma_gemm<false, 2, 4, 2, 4><<<dim3(1, NB / 32), 256, smem_g2>>>(
        hhi, hlo, w2hi, w2lo, b2, emb, ehi, elo, NE, 32, 4);
    // h2 = relu(emb @ W3 + b3) -> h2 fragments       (128x64 tiles, 256 CTAs)
    mma_gemm<true, 1, 8, 8, 2><<<dim3(4, NB / 128), 256, smem_g1>>>(
        ehi, elo, w3hi, w3lo, b3, nullptr, h2hi, h2lo, NH, 4, 32);
    // rec = h2 @ W4 + b4     -> normal output        (128x128 tiles, 448 CTAs)
    mma_gemm<false, 0, 16, 8, 2><<<dim3(7, NB / 128), 256, smem_g4>>>(
        h2hi, h2lo, w4hi, w4lo, b4, rec, nullptr, nullptr, ND, 32, 0);

    // ---- distances + softmin ----
    dist_softmin_kernel<<<NB / 64, 256>>>(emb, reps, weighted, distances);
}

// round 14
// speedup vs baseline: 1.2467x; 1.0224x over previous
#include <cuda_runtime.h>
#include <cstdint>
#include <math.h>

#define ALPHA 1000.0f
#define NB 8192
#define ND 784
#define NH 256
#define NE 32
#define NK 512

// ---------------------------------------------------------------------------
// Fragment-major hi/lo scratch (allocation-free rule: __device__ globals).
// A-frag layout: [mblk][KB][32 lanes][4]  (128 floats / block)
// B-frag layout: [nblk][KB][32 lanes][2]  (64 floats / block)
// ---------------------------------------------------------------------------
__device__ float g_xhi [NB * ND], g_xlo [NB * ND];     // x    A-frags, KB=98
__device__ float g_hhi [NB * NH], g_hlo [NB * NH];     // h    A-frags, KB=32
__device__ float g_ehi [NB * NE], g_elo [NB * NE];     // emb  A-frags, KB=4
__device__ float g_h2hi[NB * NH], g_h2lo[NB * NH];     // h2   A-frags, KB=32
__device__ float g_w1hi[32 * 98 * 64],  g_w1lo[32 * 98 * 64];    // W1 (N=256)
__device__ float g_w2hi[4 * 32 * 64],   g_w2lo[4 * 32 * 64];     // W2 (NPAD=32)
__device__ float g_w3hi[32 * 4 * 64],   g_w3lo[32 * 4 * 64];     // W3 (N=256)
__device__ float g_w4hi[112 * 32 * 64], g_w4lo[112 * 32 * 64];   // W4 (NPAD=896)

// ---------------------------------------------------------------------------
// helpers (baseline PTX only)
// ---------------------------------------------------------------------------
__device__ __forceinline__ uint32_t tf32_round(float x) {
    uint32_t u;
    asm("cvt.rna.tf32.f32 %0, %1;" : "=r"(u) : "f"(x));
    return u;
}
__device__ __forceinline__ void mma_tf32(float* d, const uint32_t* a, const uint32_t* b) {
    asm volatile(
        "mma.sync.aligned.m16n8k8.row.col.f32.tf32.tf32.f32 "
        "{%0,%1,%2,%3}, {%4,%5,%6,%7}, {%8,%9}, {%0,%1,%2,%3};"
        : "+f"(d[0]), "+f"(d[1]), "+f"(d[2]), "+f"(d[3])
        : "r"(a[0]), "r"(a[1]), "r"(a[2]), "r"(a[3]), "r"(b[0]), "r"(b[1]));
}
__device__ __forceinline__ uint32_t smem_u32(const void* p) {
    uint32_t a;
    asm("{ .reg .u64 t; cvta.to.shared.u64 t, %1; cvt.u32.u64 %0, t; }" : "=r"(a) : "l"(p));
    return a;
}
__device__ __forceinline__ void cp16(uint32_t dst, const void* src) {
    asm volatile("cp.async.cg.shared.global [%0], [%1], 16;" :: "r"(dst), "l"(src));
}

// write one value into A-fragment hi/lo buffers (for the next GEMM)
__device__ __forceinline__ void write_frag(float v, int m, int k, int KB,
                                           float* ghi, float* glo) {
    uint32_t hi = tf32_round(v);
    uint32_t lo = tf32_round(v - __uint_as_float(hi));
    const int mblk = m >> 4, kblk = k >> 3;
    const int ln   = ((m & 7) << 2) | (k & 3);
    const int slot = ((m >> 3) & 1) | (((k >> 2) & 1) << 1);
    const size_t o = (((size_t)mblk * KB + kblk) * 32 + ln) * 4 + slot;
    ((uint32_t*)ghi)[o] = hi;
    ((uint32_t*)glo)[o] = lo;
}

// ---------------------------------------------------------------------------
// split_A: A[M,K] row-major -> hi/lo A-fragments. Tile 32m x 64k per block.
// ---------------------------------------------------------------------------
__global__ __launch_bounds__(256) void split_A_kernel(
    const float* __restrict__ A, float* __restrict__ hi, float* __restrict__ lo,
    int K, int KB)
{
    __shared__ float s[32][65];
    const int tid = threadIdx.x;
    const int k0 = blockIdx.x * 64;
    const int m0 = blockIdx.y * 32;
#pragma unroll
    for (int i = 0; i < 8; i++) {
        const int idx = tid + i * 256;
        const int r = idx >> 6, cc = idx & 63;
        const int k = k0 + cc;
        s[r][cc] = (k < K) ? A[(size_t)(m0 + r) * K + k] : 0.f;
    }
    __syncthreads();
    const int mblk0 = blockIdx.y * 2, kblk0 = blockIdx.x * 8;
#pragma unroll
    for (int i = 0; i < 2; i++) {
        const int slot = tid + i * 256;       // 0..511
        const int mb = slot >> 8, kb = (slot >> 5) & 7, ln = slot & 31;
        if (kblk0 + kb < KB) {
            const int gg = ln >> 2, cc = ln & 3;
            const int mr = mb * 16 + gg, kc = kb * 8 + cc;
            const float v0 = s[mr][kc],     v1 = s[mr + 8][kc];
            const float v2 = s[mr][kc + 4], v3 = s[mr + 8][kc + 4];
            uint4 h4, l4;
            h4.x = tf32_round(v0); l4.x = tf32_round(v0 - __uint_as_float(h4.x));
            h4.y = tf32_round(v1); l4.y = tf32_round(v1 - __uint_as_float(h4.y));
            h4.z = tf32_round(v2); l4.z = tf32_round(v2 - __uint_as_float(h4.z));
            h4.w = tf32_round(v3); l4.w = tf32_round(v3 - __uint_as_float(h4.w));
            const size_t o = (((size_t)(mblk0 + mb) * KB + kblk0 + kb) * 32 + ln) * 4;
            *(uint4*)&hi[o] = h4;
            *(uint4*)&lo[o] = l4;
        }
    }
}

// ---------------------------------------------------------------------------
// merged split_B for all 4 weights: W[K,N] -> hi/lo B-fragments (pad to NPAD).
// ---------------------------------------------------------------------------
struct SplitBArgs {
    const float* W[4];
    float* hi[4];
    float* lo[4];
    int K[4], N[4], KB[4], gx[4], gy[4];
};

__global__ __launch_bounds__(256) void split_B4_kernel(SplitBArgs a)
{
    const int z = blockIdx.z;
    if ((int)blockIdx.x >= a.gx[z] || (int)blockIdx.y >= a.gy[z]) return;
    const float* __restrict__ W = a.W[z];
    float* __restrict__ hi = a.hi[z];
    float* __restrict__ lo = a.lo[z];
    const int K = a.K[z], N = a.N[z], KB = a.KB[z];

    __shared__ float s[64][33];
    const int tid = threadIdx.x;
    const int n0 = blockIdx.x * 32;
    const int k0 = blockIdx.y * 64;
#pragma unroll
    for (int i = 0; i < 8; i++) {
        const int idx = tid + i * 256;
        const int r = idx >> 5, cc = idx & 31;
        const int k = k0 + r, n = n0 + cc;
        s[r][cc] = (k < K && n < N) ? W[(size_t)k * N + n] : 0.f;
    }
    __syncthreads();
    const int nblk0 = blockIdx.x * 4, kblk0 = blockIdx.y * 8;
#pragma unroll
    for (int i = 0; i < 4; i++) {
        const int slot = tid + i * 256;       // 0..1023
        const int nb = slot >> 8, kb = (slot >> 5) & 7, ln = slot & 31;
        if (kblk0 + kb < KB) {
            const int gg = ln >> 2, cc = ln & 3;
            const float b0 = s[kb * 8 + cc][nb * 8 + gg];
            const float b1 = s[kb * 8 + cc + 4][nb * 8 + gg];
            uint2 h2, l2;
            h2.x = tf32_round(b0); l2.x = tf32_round(b0 - __uint_as_float(h2.x));
            h2.y = tf32_round(b1); l2.y = tf32_round(b1 - __uint_as_float(h2.y));
            const size_t o = (((size_t)(nblk0 + nb) * KB + kblk0 + kb) * 32 + ln) * 2;
            *(uint2*)&hi[o] = h2;
            *(uint2*)&lo[o] = l2;
        }
    }
}

// ---------------------------------------------------------------------------
// 3xTF32 GEMM on pre-split fragments, 3-stage cp.async pipeline.
// CTA tile (MBLKS*16) x (NBLKS*8), 256 threads = 8 warps (2M x 4N).
// smem: 3 stages x (2*MBLKS*1KB + 2*NBLKS*0.5KB).
// OUTMODE: 0 = normal C, 1 = A-frags of next gemm, 2 = both.
// ---------------------------------------------------------------------------
template <bool RELU, int OUTMODE, int NBLKS, int MBLKS, int OCC>
__global__ __launch_bounds__(256, OCC) void mma_gemm(
    const float* __restrict__ Ahi, const float* __restrict__ Alo,
    const float* __restrict__ Bhi, const float* __restrict__ Blo,
    const float* __restrict__ bias,
    float* __restrict__ Cn, float* __restrict__ Chi, float* __restrict__ Clo,
    int N, int KB, int KBOUT)
{
    constexpr int NTW = NBLKS / 4;    // nblks per warp
    constexpr int MT  = MBLKS / 2;    // mtiles (16 rows each) per warp
    constexpr int A_BYTES = MBLKS * 1024;
    constexpr int B_BYTES = NBLKS * 512;
    constexpr int STAGE   = 2 * A_BYTES + 2 * B_BYTES;

    extern __shared__ char smem[];
    const uint32_t sb32 = smem_u32(smem);
    const int tid = threadIdx.x, wid = tid >> 5, lane = tid & 31;
    const int wm = wid & 1, wn = wid >> 1;
    const int g = lane >> 2, c = lane & 3;
    const int m0 = blockIdx.y * MBLKS * 16, n0 = blockIdx.x * NBLKS * 8;
    const int mblk0 = blockIdx.y * MBLKS, nblk0 = blockIdx.x * NBLKS;

    float acc[MT][NTW][4];
#pragma unroll
    for (int mt = 0; mt < MT; mt++)
#pragma unroll
        for (int nt = 0; nt < NTW; nt++)
#pragma unroll
            for (int i = 0; i < 4; i++) acc[mt][nt][i] = 0.f;

    const int nch = KB >> 1;

    auto issue = [&](int t) {
        const uint32_t s = sb32 + (t % 3) * STAGE;
        const int kb0 = t * 2;
        // A: MBLKS*64 cp16 (MBLKS mblks x 2 kblks x 128 floats)
#pragma unroll
        for (int idx = tid; idx < MBLKS * 64; idx += 256) {
            const int mb = idx >> 6, off = idx & 63;
            const size_t go = ((size_t)(mblk0 + mb) * KB + kb0) * 128 + off * 4;
            cp16(s + idx * 16,           Ahi + go);
            cp16(s + A_BYTES + idx * 16, Alo + go);
        }
        // B: NBLKS*32 cp16 (NBLKS nblks x 2 kblks x 64 floats)
#pragma unroll
        for (int idx = tid; idx < NBLKS * 32; idx += 256) {
            const int nb = idx >> 5, off = idx & 31;
            const size_t go = ((size_t)(nblk0 + nb) * KB + kb0) * 64 + off * 4;
            cp16(s + 2 * A_BYTES + idx * 16,           Bhi + go);
            cp16(s + 2 * A_BYTES + B_BYTES + idx * 16, Blo + go);
        }
    };

    int issued = 0;
    const int pre = (nch < 2) ? nch : 2;
    for (; issued < pre; issued++) {
        issue(issued);
        asm volatile("cp.async.commit_group;");
    }

    for (int t = 0; t < nch; t++) {
        if (issued < nch) {
            issue(issued);
            asm volatile("cp.async.commit_group;");
            issued++;
        }
        const int pending = issued - t - 1;
        if (pending >= 2)      asm volatile("cp.async.wait_group 2;");
        else if (pending == 1) asm volatile("cp.async.wait_group 1;");
        else                   asm volatile("cp.async.wait_group 0;");
        __syncthreads();

        const char* s = smem + (t % 3) * STAGE;
#pragma unroll
        for (int ks = 0; ks < 2; ks++) {
            uint4 ah[MT], al[MT];
#pragma unroll
            for (int mt = 0; mt < MT; mt++) {
                const int off = (((wm * MT + mt) * 2 + ks) * 32 + lane) * 16;
                ah[mt] = *(const uint4*)(s + off);
                al[mt] = *(const uint4*)(s + A_BYTES + off);
            }
            uint2 bh[NTW], bl[NTW];
#pragma unroll
            for (int nt = 0; nt < NTW; nt++) {
                const int off = (((wn * NTW + nt) * 2 + ks) * 32 + lane) * 8;
                bh[nt] = *(const uint2*)(s + 2 * A_BYTES + off);
                bl[nt] = *(const uint2*)(s + 2 * A_BYTES + B_BYTES + off);
            }
#pragma unroll
            for (int mt = 0; mt < MT; mt++)
#pragma unroll
                for (int nt = 0; nt < NTW; nt++) {
                    mma_tf32(acc[mt][nt], (const uint32_t*)&ah[mt], (const uint32_t*)&bh[nt]);
                    mma_tf32(acc[mt][nt], (const uint32_t*)&ah[mt], (const uint32_t*)&bl[nt]);
                    mma_tf32(acc[mt][nt], (const uint32_t*)&al[mt], (const uint32_t*)&bh[nt]);
                }
        }
        __syncthreads();
    }

    // ---- epilogue ----
#pragma unroll
    for (int nt = 0; nt < NTW; nt++) {
        const int col = n0 + (wn * NTW + nt) * 8 + 2 * c;
        if (col < N) {
            const float bx = __ldg(&bias[col]);
            const float by = __ldg(&bias[col + 1]);
#pragma unroll
            for (int mt = 0; mt < MT; mt++) {
                const int row = m0 + (wm * MT + mt) * 16 + g;
                float v00 = acc[mt][nt][0] + bx;
                float v01 = acc[mt][nt][1] + by;
                float v10 = acc[mt][nt][2] + bx;
                float v11 = acc[mt][nt][3] + by;
                if (RELU) {
                    v00 = fmaxf(v00, 0.f); v01 = fmaxf(v01, 0.f);
                    v10 = fmaxf(v10, 0.f); v11 = fmaxf(v11, 0.f);
                }
                if (OUTMODE == 0 || OUTMODE == 2) {
                    *(float2*)&Cn[(size_t)row * N + col]       = make_float2(v00, v01);
                    *(float2*)&Cn[(size_t)(row + 8) * N + col] = make_float2(v10, v11);
                }
                if (OUTMODE == 1 || OUTMODE == 2) {
                    write_frag(v00, row,     col,     KBOUT, Chi, Clo);
                    write_frag(v01, row,     col + 1, KBOUT, Chi, Clo);
                    write_frag(v10, row + 8, col,     KBOUT, Chi, Clo);
                    write_frag(v11, row + 8, col + 1, KBOUT, Chi, Clo);
                }
            }
        }
    }
}

// ---------------------------------------------------------------------------
// Dist v4: dot-product form, reps register-resident (2 clusters/thread),
// exp computed ONCE per element (cached in regs) via __expf.
// Block = 256 threads, 32 rows (4 groups of 8); 256 blocks fill the chip.
// ---------------------------------------------------------------------------
__global__ __launch_bounds__(256) void dist_softmin_kernel(
    const float* __restrict__ emb, const float* __restrict__ reps,
    float* __restrict__ weighted, float* __restrict__ distances)
{
    __shared__ float emb_s[32 * NE];     // 4KB
    __shared__ float en_s[32];
    __shared__ float red_s[8 * 8];       // [warp][row-in-group]
    __shared__ float rmin_s[8], rsum_s[8];

    const int tid  = threadIdx.x;
    const int wid  = tid >> 5;
    const int lane = tid & 31;
    const int brow = blockIdx.x * 32;
    const int c0   = tid * 2;

    // load 2 cluster reps into registers + norms
    float r0[NE], r1[NE];
    float rn0 = 0.f, rn1 = 0.f;
    const float4* rp0 = (const float4*)(reps + (size_t)c0 * NE);
    const float4* rp1 = (const float4*)(reps + (size_t)(c0 + 1) * NE);
#pragma unroll
    for (int e4 = 0; e4 < 8; e4++) {
        float4 a = rp0[e4], b = rp1[e4];
        r0[e4*4+0] = a.x; r0[e4*4+1] = a.y; r0[e4*4+2] = a.z; r0[e4*4+3] = a.w;
        r1[e4*4+0] = b.x; r1[e4*4+1] = b.y; r1[e4*4+2] = b.z; r1[e4*4+3] = b.w;
        rn0 = fmaf(a.x, a.x, rn0); rn0 = fmaf(a.y, a.y, rn0);
        rn0 = fmaf(a.z, a.z, rn0); rn0 = fmaf(a.w, a.w, rn0);
        rn1 = fmaf(b.x, b.x, rn1); rn1 = fmaf(b.y, b.y, rn1);
        rn1 = fmaf(b.z, b.z, rn1); rn1 = fmaf(b.w, b.w, rn1);
    }

    // stage 32 emb rows
    const float4* embg = (const float4*)(emb + (size_t)brow * NE);
    {
        const int idx = tid;   // 256 threads cover 32*32/4 = 256 float4s
        ((float4*)emb_s)[idx] = embg[idx];
    }
    __syncthreads();
    // row norms
    if (tid < 32) {
        const float4* ep = (const float4*)(emb_s + tid * NE);
        float s = 0.f;
#pragma unroll
        for (int e4 = 0; e4 < 8; e4++) {
            float4 v = ep[e4];
            s = fmaf(v.x, v.x, s); s = fmaf(v.y, v.y, s);
            s = fmaf(v.z, v.z, s); s = fmaf(v.w, v.w, s);
        }
        en_s[tid] = s;
    }
    __syncthreads();

#pragma unroll 1
    for (int gq = 0; gq < 4; gq++) {
        float d0[8], d1[8];
#pragma unroll
        for (int i = 0; i < 8; i++) {
            const int r = gq * 8 + i;
            const float4* ep = (const float4*)(emb_s + r * NE);
            float dot0 = 0.f, dot1 = 0.f;
#pragma unroll
            for (int e4 = 0; e4 < 8; e4++) {
                float4 ev = ep[e4];   // broadcast LDS.128
                dot0 = fmaf(ev.x, r0[e4*4+0], dot0);
                dot0 = fmaf(ev.y, r0[e4*4+1], dot0);
                dot0 = fmaf(ev.z, r0[e4*4+2], dot0);
                dot0 = fmaf(ev.w, r0[e4*4+3], dot0);
                dot1 = fmaf(ev.x, r1[e4*4+0], dot1);
                dot1 = fmaf(ev.y, r1[e4*4+1], dot1);
                dot1 = fmaf(ev.z, r1[e4*4+2], dot1);
                dot1 = fmaf(ev.w, r1[e4*4+3], dot1);
            }
            const float en = en_s[r];
            d0[i] = fmaf(-2.f, dot0, en + rn0);
            d1[i] = fmaf(-2.f, dot1, en + rn1);
        }

        // block-wide min per row
#pragma unroll
        for (int i = 0; i < 8; i++) {
            float v = fminf(d0[i], d1[i]);
#pragma unroll
            for (int o = 16; o > 0; o >>= 1)
                v = fminf(v, __shfl_xor_sync(0xFFFFFFFF, v, o));
            if (lane == 0) red_s[wid * 8 + i] = v;
        }
        __syncthreads();
        if (tid < 8) {
            float m = red_s[tid];
#pragma unroll
            for (int w = 1; w < 8; w++) m = fminf(m, red_s[w * 8 + tid]);
            rmin_s[tid] = m;
        }
        __syncthreads();

        // block-wide exp-sum per row; exp cached in registers (single MUFU each)
        float e0[8], e1[8];
#pragma unroll
        for (int i = 0; i < 8; i++) {
            const float mv = rmin_s[i];
            e0[i] = __expf(-ALPHA * (d0[i] - mv));
            e1[i] = __expf(-ALPHA * (d1[i] - mv));
            float ps = e0[i] + e1[i];
#pragma unroll
            for (int o = 16; o > 0; o >>= 1)
                ps += __shfl_xor_sync(0xFFFFFFFF, ps, o);
            if (lane == 0) red_s[wid * 8 + i] = ps;
        }
        __syncthreads();
        if (tid < 8) {
            float s = red_s[tid];
#pragma unroll
            for (int w = 1; w < 8; w++) s += red_s[w * 8 + tid];
            rsum_s[tid] = s;
        }
        __syncthreads();

        // stores (float2, coalesced) using cached exps
#pragma unroll
        for (int i = 0; i < 8; i++) {
            const float inv = 1.0f / rsum_s[i];
            const float dv0 = d0[i], dv1 = d1[i];
            const size_t base = (size_t)(brow + gq * 8 + i) * NK + c0;
            *(float2*)&distances[base] = make_float2(dv0, dv1);
            *(float2*)&weighted[base]  = make_float2(
                dv0 * e0[i] * inv,
                dv1 * e1[i] * inv);
        }
        __syncthreads();   // protect rmin_s/rsum_s/red_s before next group
    }
}

// ---------------------------------------------------------------------------
extern "C" void kernel_launch(void* const* d_in, const int* in_sizes, int n_in,
                              void* d_out, int out_size)
{
    const float* x    = (const float*)d_in[0];
    const float* reps = (const float*)d_in[1];
    const float* W1   = (const float*)d_in[2];
    const float* b1   = (const float*)d_in[3];
    const float* W2   = (const float*)d_in[4];
    const float* b2   = (const float*)d_in[5];
    const float* W3   = (const float*)d_in[6];
    const float* b3   = (const float*)d_in[7];
    const float* W4   = (const float*)d_in[8];
    const float* b4   = (const float*)d_in[9];

    float* out       = (float*)d_out;
    float* weighted  = out;
    float* distances = out + (size_t)NB * NK;
    float* rec       = out + 2 * (size_t)NB * NK;
    float* emb       = out + 2 * (size_t)NB * NK + (size_t)NB * ND;

    float *xhi, *xlo, *hhi, *hlo, *ehi, *elo, *h2hi, *h2lo;
    float *w1hi, *w1lo, *w2hi, *w2lo, *w3hi, *w3lo, *w4hi, *w4lo;
    cudaGetSymbolAddress((void**)&xhi,  g_xhi);  cudaGetSymbolAddress((void**)&xlo,  g_xlo);
    cudaGetSymbolAddress((void**)&hhi,  g_hhi);  cudaGetSymbolAddress((void**)&hlo,  g_hlo);
    cudaGetSymbolAddress((void**)&ehi,  g_ehi);  cudaGetSymbolAddress((void**)&elo,  g_elo);
    cudaGetSymbolAddress((void**)&h2hi, g_h2hi); cudaGetSymbolAddress((void**)&h2lo, g_h2lo);
    cudaGetSymbolAddress((void**)&w1hi, g_w1hi); cudaGetSymbolAddress((void**)&w1lo, g_w1lo);
    cudaGetSymbolAddress((void**)&w2hi, g_w2hi); cudaGetSymbolAddress((void**)&w2lo, g_w2lo);
    cudaGetSymbolAddress((void**)&w3hi, g_w3hi); cudaGetSymbolAddress((void**)&w3lo, g_w3lo);
    cudaGetSymbolAddress((void**)&w4hi, g_w4hi); cudaGetSymbolAddress((void**)&w4lo, g_w4lo);

    // smem sizes: 3 stages * (2*MBLKS*1024 + 2*NBLKS*512)
    const int smem_g1 = 3 * (2 * 8 * 1024 + 2 * 8 * 512);    // 73728
    const int smem_g2 = 3 * (2 * 2 * 1024 + 2 * 4 * 512);    // 24576
    const int smem_g4 = 3 * (2 * 8 * 1024 + 2 * 16 * 512);   // 98304
    cudaFuncSetAttribute((const void*)mma_gemm<true, 1, 8, 8, 2>,
                         cudaFuncAttributeMaxDynamicSharedMemorySize, smem_g1);
    cudaFuncSetAttribute((const void*)mma_gemm<false, 2, 4, 2, 4>,
                         cudaFuncAttributeMaxDynamicSharedMemorySize, smem_g2);
    cudaFuncSetAttribute((const void*)mma_gemm<false, 0, 16, 8, 2>,
                         cudaFuncAttributeMaxDynamicSharedMemorySize, smem_g4);

    // ---- operand pre-splits ----
    split_A_kernel<<<dim3(13, NB / 32), 256>>>(x, xhi, xlo, ND, 98);
    {
        SplitBArgs a;
        a.W[0] = W1;   a.hi[0] = w1hi; a.lo[0] = w1lo;
        a.K[0] = ND;   a.N[0] = NH;    a.KB[0] = 98; a.gx[0] = 8;  a.gy[0] = 13;
        a.W[1] = W2;   a.hi[1] = w2hi; a.lo[1] = w2lo;
        a.K[1] = NH;   a.N[1] = NE;    a.KB[1] = 32; a.gx[1] = 1;  a.gy[1] = 4;
        a.W[2] = W3;   a.hi[2] = w3hi; a.lo[2] = w3lo;
        a.K[2] = NE;   a.N[2] = NH;    a.KB[2] = 4;  a.gx[2] = 8;  a.gy[2] = 1;
        a.W[3] = W4;   a.hi[3] = w4hi; a.lo[3] = w4lo;
        a.K[3] = NH;   a.N[3] = ND;    a.KB[3] = 32; a.gx[3] = 28; a.gy[3] = 4;
        split_B4_kernel<<<dim3(28, 13, 4), 256>>>(a);
    }

    // ---- GEMM chain ----
    // h = relu(x @ W1 + b1)  -> h fragments          (128x64 tiles, 256 CTAs)
    mma_gemm<true, 1, 8, 8, 2><<<dim3(4, NB / 128), 256, smem_g1>>>(
        xhi, xlo, w1hi, w1lo, b1, nullptr, hhi, hlo, NH, 98, 32);
    // emb = h @ W2 + b2      -> normal emb + emb fragments (32x32 tiles, 256 CTAs)
    mma_gemm<false, 2, 4, 2, 4><<<dim3(1, NB / 32), 256, smem_g2>>>(
        hhi, hlo, w2hi, w2lo, b2, emb, ehi, elo, NE, 32, 4);
    // h2 = relu(emb @ W3 + b3) -> h2 fragments       (128x64 tiles, 256 CTAs)
    mma_gemm<true, 1, 8, 8, 2><<<dim3(4, NB / 128), 256, smem_g1>>>(
        ehi, elo, w3hi, w3lo, b3, nullptr, h2hi, h2lo, NH, 4, 32);
    // rec = h2 @ W4 + b4     -> normal output        (128x128 tiles, 448 CTAs)
    mma_gemm<false, 0, 16, 8, 2><<<dim3(7, NB / 128), 256, smem_g4>>>(
        h2hi, h2lo, w4hi, w4lo, b4, rec, nullptr, nullptr, ND, 32, 0);

    // ---- distances + softmin ----
    dist_softmin_kernel<<<NB / 32, 256>>>(emb, reps, weighted, distances);
}

// round 16
// speedup vs baseline: 1.2778x; 1.0249x over previous
#include <cuda_runtime.h>
#include <cstdint>
#include <math.h>

#define ALPHA 1000.0f
#define NB 8192
#define ND 784
#define NH 256
#define NE 32
#define NK 512

// ---------------------------------------------------------------------------
// Fragment-major hi/lo scratch (allocation-free rule: __device__ globals).
// A-frag layout: [mblk][KB][32 lanes][4]  (128 floats / block)
// B-frag layout: [nblk][KB][32 lanes][2]  (64 floats / block)
// ---------------------------------------------------------------------------
__device__ float g_xhi [NB * ND], g_xlo [NB * ND];     // x    A-frags, KB=98
__device__ float g_hhi [NB * NH], g_hlo [NB * NH];     // h    A-frags, KB=32
__device__ float g_ehi [NB * NE], g_elo [NB * NE];     // emb  A-frags, KB=4
__device__ float g_h2hi[NB * NH], g_h2lo[NB * NH];     // h2   A-frags, KB=32
__device__ float g_w1hi[32 * 98 * 64],  g_w1lo[32 * 98 * 64];    // W1 (N=256)
__device__ float g_w2hi[4 * 32 * 64],   g_w2lo[4 * 32 * 64];     // W2 (NPAD=32)
__device__ float g_w3hi[32 * 4 * 64],   g_w3lo[32 * 4 * 64];     // W3 (N=256)
__device__ float g_w4hi[112 * 32 * 64], g_w4lo[112 * 32 * 64];   // W4 (NPAD=896)

// ---------------------------------------------------------------------------
// helpers (baseline PTX only)
// ---------------------------------------------------------------------------
__device__ __forceinline__ uint32_t tf32_round(float x) {
    uint32_t u;
    asm("cvt.rna.tf32.f32 %0, %1;" : "=r"(u) : "f"(x));
    return u;
}
__device__ __forceinline__ void mma_tf32(float* d, const uint32_t* a, const uint32_t* b) {
    asm volatile(
        "mma.sync.aligned.m16n8k8.row.col.f32.tf32.tf32.f32 "
        "{%0,%1,%2,%3}, {%4,%5,%6,%7}, {%8,%9}, {%0,%1,%2,%3};"
        : "+f"(d[0]), "+f"(d[1]), "+f"(d[2]), "+f"(d[3])
        : "r"(a[0]), "r"(a[1]), "r"(a[2]), "r"(a[3]), "r"(b[0]), "r"(b[1]));
}
__device__ __forceinline__ uint32_t smem_u32(const void* p) {
    uint32_t a;
    asm("{ .reg .u64 t; cvta.to.shared.u64 t, %1; cvt.u32.u64 %0, t; }" : "=r"(a) : "l"(p));
    return a;
}
__device__ __forceinline__ void cp16(uint32_t dst, const void* src) {
    asm volatile("cp.async.cg.shared.global [%0], [%1], 16;" :: "r"(dst), "l"(src));
}

// write one value into A-fragment hi/lo buffers (for the next GEMM)
__device__ __forceinline__ void write_frag(float v, int m, int k, int KB,
                                           float* ghi, float* glo) {
    uint32_t hi = tf32_round(v);
    uint32_t lo = tf32_round(v - __uint_as_float(hi));
    const int mblk = m >> 4, kblk = k >> 3;
    const int ln   = ((m & 7) << 2) | (k & 3);
    const int slot = ((m >> 3) & 1) | (((k >> 2) & 1) << 1);
    const size_t o = (((size_t)mblk * KB + kblk) * 32 + ln) * 4 + slot;
    ((uint32_t*)ghi)[o] = hi;
    ((uint32_t*)glo)[o] = lo;
}

// ---------------------------------------------------------------------------
// split_A: A[M,K] row-major -> hi/lo A-fragments. Tile 32m x 64k per block.
// ---------------------------------------------------------------------------
__global__ __launch_bounds__(256) void split_A_kernel(
    const float* __restrict__ A, float* __restrict__ hi, float* __restrict__ lo,
    int K, int KB)
{
    __shared__ float s[32][65];
    const int tid = threadIdx.x;
    const int k0 = blockIdx.x * 64;
    const int m0 = blockIdx.y * 32;
#pragma unroll
    for (int i = 0; i < 8; i++) {
        const int idx = tid + i * 256;
        const int r = idx >> 6, cc = idx & 63;
        const int k = k0 + cc;
        s[r][cc] = (k < K) ? A[(size_t)(m0 + r) * K + k] : 0.f;
    }
    __syncthreads();
    const int mblk0 = blockIdx.y * 2, kblk0 = blockIdx.x * 8;
#pragma unroll
    for (int i = 0; i < 2; i++) {
        const int slot = tid + i * 256;       // 0..511
        const int mb = slot >> 8, kb = (slot >> 5) & 7, ln = slot & 31;
        if (kblk0 + kb < KB) {
            const int gg = ln >> 2, cc = ln & 3;
            const int mr = mb * 16 + gg, kc = kb * 8 + cc;
            const float v0 = s[mr][kc],     v1 = s[mr + 8][kc];
            const float v2 = s[mr][kc + 4], v3 = s[mr + 8][kc + 4];
            uint4 h4, l4;
            h4.x = tf32_round(v0); l4.x = tf32_round(v0 - __uint_as_float(h4.x));
            h4.y = tf32_round(v1); l4.y = tf32_round(v1 - __uint_as_float(h4.y));
            h4.z = tf32_round(v2); l4.z = tf32_round(v2 - __uint_as_float(h4.z));
            h4.w = tf32_round(v3); l4.w = tf32_round(v3 - __uint_as_float(h4.w));
            const size_t o = (((size_t)(mblk0 + mb) * KB + kblk0 + kb) * 32 + ln) * 4;
            *(uint4*)&hi[o] = h4;
            *(uint4*)&lo[o] = l4;
        }
    }
}

// ---------------------------------------------------------------------------
// merged split_B for all 4 weights: W[K,N] -> hi/lo B-fragments (pad to NPAD).
// ---------------------------------------------------------------------------
struct SplitBArgs {
    const float* W[4];
    float* hi[4];
    float* lo[4];
    int K[4], N[4], KB[4], gx[4], gy[4];
};

__global__ __launch_bounds__(256) void split_B4_kernel(SplitBArgs a)
{
    const int z = blockIdx.z;
    if ((int)blockIdx.x >= a.gx[z] || (int)blockIdx.y >= a.gy[z]) return;
    const float* __restrict__ W = a.W[z];
    float* __restrict__ hi = a.hi[z];
    float* __restrict__ lo = a.lo[z];
    const int K = a.K[z], N = a.N[z], KB = a.KB[z];

    __shared__ float s[64][33];
    const int tid = threadIdx.x;
    const int n0 = blockIdx.x * 32;
    const int k0 = blockIdx.y * 64;
#pragma unroll
    for (int i = 0; i < 8; i++) {
        const int idx = tid + i * 256;
        const int r = idx >> 5, cc = idx & 31;
        const int k = k0 + r, n = n0 + cc;
        s[r][cc] = (k < K && n < N) ? W[(size_t)k * N + n] : 0.f;
    }
    __syncthreads();
    const int nblk0 = blockIdx.x * 4, kblk0 = blockIdx.y * 8;
#pragma unroll
    for (int i = 0; i < 4; i++) {
        const int slot = tid + i * 256;       // 0..1023
        const int nb = slot >> 8, kb = (slot >> 5) & 7, ln = slot & 31;
        if (kblk0 + kb < KB) {
            const int gg = ln >> 2, cc = ln & 3;
            const float b0 = s[kb * 8 + cc][nb * 8 + gg];
            const float b1 = s[kb * 8 + cc + 4][nb * 8 + gg];
            uint2 h2, l2;
            h2.x = tf32_round(b0); l2.x = tf32_round(b0 - __uint_as_float(h2.x));
            h2.y = tf32_round(b1); l2.y = tf32_round(b1 - __uint_as_float(h2.y));
            const size_t o = (((size_t)(nblk0 + nb) * KB + kblk0 + kb) * 32 + ln) * 2;
            *(uint2*)&hi[o] = h2;
            *(uint2*)&lo[o] = l2;
        }
    }
}

// ---------------------------------------------------------------------------
// 3xTF32 GEMM on pre-split fragments, 3-stage cp.async pipeline.
// CTA tile (MBLKS*16) x (NBLKS*8), 256 threads = 8 warps (2M x 4N).
// smem: 3 stages x (2*MBLKS*1KB + 2*NBLKS*0.5KB).
// OUTMODE: 0 = normal C, 1 = A-frags of next gemm, 2 = both.
// ---------------------------------------------------------------------------
template <bool RELU, int OUTMODE, int NBLKS, int MBLKS, int OCC>
__global__ __launch_bounds__(256, OCC) void mma_gemm(
    const float* __restrict__ Ahi, const float* __restrict__ Alo,
    const float* __restrict__ Bhi, const float* __restrict__ Blo,
    const float* __restrict__ bias,
    float* __restrict__ Cn, float* __restrict__ Chi, float* __restrict__ Clo,
    int N, int KB, int KBOUT)
{
    constexpr int NTW = NBLKS / 4;    // nblks per warp
    constexpr int MT  = MBLKS / 2;    // mtiles (16 rows each) per warp
    constexpr int A_BYTES = MBLKS * 1024;
    constexpr int B_BYTES = NBLKS * 512;
    constexpr int STAGE   = 2 * A_BYTES + 2 * B_BYTES;

    extern __shared__ char smem[];
    const uint32_t sb32 = smem_u32(smem);
    const int tid = threadIdx.x, wid = tid >> 5, lane = tid & 31;
    const int wm = wid & 1, wn = wid >> 1;
    const int g = lane >> 2, c = lane & 3;
    const int m0 = blockIdx.y * MBLKS * 16, n0 = blockIdx.x * NBLKS * 8;
    const int mblk0 = blockIdx.y * MBLKS, nblk0 = blockIdx.x * NBLKS;

    float acc[MT][NTW][4];
#pragma unroll
    for (int mt = 0; mt < MT; mt++)
#pragma unroll
        for (int nt = 0; nt < NTW; nt++)
#pragma unroll
            for (int i = 0; i < 4; i++) acc[mt][nt][i] = 0.f;

    const int nch = KB >> 1;

    auto issue = [&](int t) {
        const uint32_t s = sb32 + (t % 3) * STAGE;
        const int kb0 = t * 2;
        // A: MBLKS*64 cp16 (MBLKS mblks x 2 kblks x 128 floats)
#pragma unroll
        for (int idx = tid; idx < MBLKS * 64; idx += 256) {
            const int mb = idx >> 6, off = idx & 63;
            const size_t go = ((size_t)(mblk0 + mb) * KB + kb0) * 128 + off * 4;
            cp16(s + idx * 16,           Ahi + go);
            cp16(s + A_BYTES + idx * 16, Alo + go);
        }
        // B: NBLKS*32 cp16 (NBLKS nblks x 2 kblks x 64 floats)
#pragma unroll
        for (int idx = tid; idx < NBLKS * 32; idx += 256) {
            const int nb = idx >> 5, off = idx & 31;
            const size_t go = ((size_t)(nblk0 + nb) * KB + kb0) * 64 + off * 4;
            cp16(s + 2 * A_BYTES + idx * 16,           Bhi + go);
            cp16(s + 2 * A_BYTES + B_BYTES + idx * 16, Blo + go);
        }
    };

    int issued = 0;
    const int pre = (nch < 2) ? nch : 2;
    for (; issued < pre; issued++) {
        issue(issued);
        asm volatile("cp.async.commit_group;");
    }

    for (int t = 0; t < nch; t++) {
        if (issued < nch) {
            issue(issued);
            asm volatile("cp.async.commit_group;");
            issued++;
        }
        const int pending = issued - t - 1;
        if (pending >= 2)      asm volatile("cp.async.wait_group 2;");
        else if (pending == 1) asm volatile("cp.async.wait_group 1;");
        else                   asm volatile("cp.async.wait_group 0;");
        __syncthreads();

        const char* s = smem + (t % 3) * STAGE;
#pragma unroll
        for (int ks = 0; ks < 2; ks++) {
            uint4 ah[MT], al[MT];
#pragma unroll
            for (int mt = 0; mt < MT; mt++) {
                const int off = (((wm * MT + mt) * 2 + ks) * 32 + lane) * 16;
                ah[mt] = *(const uint4*)(s + off);
                al[mt] = *(const uint4*)(s + A_BYTES + off);
            }
            uint2 bh[NTW], bl[NTW];
#pragma unroll
            for (int nt = 0; nt < NTW; nt++) {
                const int off = (((wn * NTW + nt) * 2 + ks) * 32 + lane) * 8;
                bh[nt] = *(const uint2*)(s + 2 * A_BYTES + off);
                bl[nt] = *(const uint2*)(s + 2 * A_BYTES + B_BYTES + off);
            }
#pragma unroll
            for (int mt = 0; mt < MT; mt++)
#pragma unroll
                for (int nt = 0; nt < NTW; nt++) {
                    mma_tf32(acc[mt][nt], (const uint32_t*)&ah[mt], (const uint32_t*)&bh[nt]);
                    mma_tf32(acc[mt][nt], (const uint32_t*)&ah[mt], (const uint32_t*)&bl[nt]);
                    mma_tf32(acc[mt][nt], (const uint32_t*)&al[mt], (const uint32_t*)&bh[nt]);
                }
        }
        __syncthreads();
    }

    // ---- epilogue ----
#pragma unroll
    for (int nt = 0; nt < NTW; nt++) {
        const int col = n0 + (wn * NTW + nt) * 8 + 2 * c;
        if (col < N) {
            const float bx = __ldg(&bias[col]);
            const float by = __ldg(&bias[col + 1]);
#pragma unroll
            for (int mt = 0; mt < MT; mt++) {
                const int row = m0 + (wm * MT + mt) * 16 + g;
                float v00 = acc[mt][nt][0] + bx;
                float v01 = acc[mt][nt][1] + by;
                float v10 = acc[mt][nt][2] + bx;
                float v11 = acc[mt][nt][3] + by;
                if (RELU) {
                    v00 = fmaxf(v00, 0.f); v01 = fmaxf(v01, 0.f);
                    v10 = fmaxf(v10, 0.f); v11 = fmaxf(v11, 0.f);
                }
                if (OUTMODE == 0 || OUTMODE == 2) {
                    *(float2*)&Cn[(size_t)row * N + col]       = make_float2(v00, v01);
                    *(float2*)&Cn[(size_t)(row + 8) * N + col] = make_float2(v10, v11);
                }
                if (OUTMODE == 1 || OUTMODE == 2) {
                    write_frag(v00, row,     col,     KBOUT, Chi, Clo);
                    write_frag(v01, row,     col + 1, KBOUT, Chi, Clo);
                    write_frag(v10, row + 8, col,     KBOUT, Chi, Clo);
                    write_frag(v11, row + 8, col + 1, KBOUT, Chi, Clo);
                }
            }
        }
    }
}

// ---------------------------------------------------------------------------
// Dist v4: dot-product form, reps register-resident (2 clusters/thread),
// exp computed ONCE per element (cached in regs) via __expf.
// Block = 256 threads, 32 rows (4 groups of 8); 256 blocks fill the chip.
// ---------------------------------------------------------------------------
__global__ __launch_bounds__(256) void dist_softmin_kernel(
    const float* __restrict__ emb, const float* __restrict__ reps,
    float* __restrict__ weighted, float* __restrict__ distances)
{
    __shared__ float emb_s[32 * NE];     // 4KB
    __shared__ float en_s[32];
    __shared__ float red_s[8 * 8];       // [warp][row-in-group]
    __shared__ float rmin_s[8], rsum_s[8];

    const int tid  = threadIdx.x;
    const int wid  = tid >> 5;
    const int lane = tid & 31;
    const int brow = blockIdx.x * 32;
    const int c0   = tid * 2;

    // load 2 cluster reps into registers + norms
    float r0[NE], r1[NE];
    float rn0 = 0.f, rn1 = 0.f;
    const float4* rp0 = (const float4*)(reps + (size_t)c0 * NE);
    const float4* rp1 = (const float4*)(reps + (size_t)(c0 + 1) * NE);
#pragma unroll
    for (int e4 = 0; e4 < 8; e4++) {
        float4 a = rp0[e4], b = rp1[e4];
        r0[e4*4+0] = a.x; r0[e4*4+1] = a.y; r0[e4*4+2] = a.z; r0[e4*4+3] = a.w;
        r1[e4*4+0] = b.x; r1[e4*4+1] = b.y; r1[e4*4+2] = b.z; r1[e4*4+3] = b.w;
        rn0 = fmaf(a.x, a.x, rn0); rn0 = fmaf(a.y, a.y, rn0);
        rn0 = fmaf(a.z, a.z, rn0); rn0 = fmaf(a.w, a.w, rn0);
        rn1 = fmaf(b.x, b.x, rn1); rn1 = fmaf(b.y, b.y, rn1);
        rn1 = fmaf(b.z, b.z, rn1); rn1 = fmaf(b.w, b.w, rn1);
    }

    // stage 32 emb rows
    const float4* embg = (const float4*)(emb + (size_t)brow * NE);
    {
        const int idx = tid;   // 256 threads cover 32*32/4 = 256 float4s
        ((float4*)emb_s)[idx] = embg[idx];
    }
    __syncthreads();
    // row norms
    if (tid < 32) {
        const float4* ep = (const float4*)(emb_s + tid * NE);
        float s = 0.f;
#pragma unroll
        for (int e4 = 0; e4 < 8; e4++) {
            float4 v = ep[e4];
            s = fmaf(v.x, v.x, s); s = fmaf(v.y, v.y, s);
            s = fmaf(v.z, v.z, s); s = fmaf(v.w, v.w, s);
        }
        en_s[tid] = s;
    }
    __syncthreads();

#pragma unroll 1
    for (int gq = 0; gq < 4; gq++) {
        float d0[8], d1[8];
#pragma unroll
        for (int i = 0; i < 8; i++) {
            const int r = gq * 8 + i;
            const float4* ep = (const float4*)(emb_s + r * NE);
            float dot0 = 0.f, dot1 = 0.f;
#pragma unroll
            for (int e4 = 0; e4 < 8; e4++) {
                float4 ev = ep[e4];   // broadcast LDS.128
                dot0 = fmaf(ev.x, r0[e4*4+0], dot0);
                dot0 = fmaf(ev.y, r0[e4*4+1], dot0);
                dot0 = fmaf(ev.z, r0[e4*4+2], dot0);
                dot0 = fmaf(ev.w, r0[e4*4+3], dot0);
                dot1 = fmaf(ev.x, r1[e4*4+0], dot1);
                dot1 = fmaf(ev.y, r1[e4*4+1], dot1);
                dot1 = fmaf(ev.z, r1[e4*4+2], dot1);
                dot1 = fmaf(ev.w, r1[e4*4+3], dot1);
            }
            const float en = en_s[r];
            d0[i] = fmaf(-2.f, dot0, en + rn0);
            d1[i] = fmaf(-2.f, dot1, en + rn1);
        }

        // block-wide min per row
#pragma unroll
        for (int i = 0; i < 8; i++) {
            float v = fminf(d0[i], d1[i]);
#pragma unroll
            for (int o = 16; o > 0; o >>= 1)
                v = fminf(v, __shfl_xor_sync(0xFFFFFFFF, v, o));
            if (lane == 0) red_s[wid * 8 + i] = v;
        }
        __syncthreads();
        if (tid < 8) {
            float m = red_s[tid];
#pragma unroll
            for (int w = 1; w < 8; w++) m = fminf(m, red_s[w * 8 + tid]);
            rmin_s[tid] = m;
        }
        __syncthreads();

        // block-wide exp-sum per row; exp cached in registers (single MUFU each)
        float e0[8], e1[8];
#pragma unroll
        for (int i = 0; i < 8; i++) {
            const float mv = rmin_s[i];
            e0[i] = __expf(-ALPHA * (d0[i] - mv));
            e1[i] = __expf(-ALPHA * (d1[i] - mv));
            float ps = e0[i] + e1[i];
#pragma unroll
            for (int o = 16; o > 0; o >>= 1)
                ps += __shfl_xor_sync(0xFFFFFFFF, ps, o);
            if (lane == 0) red_s[wid * 8 + i] = ps;
        }
        __syncthreads();
        if (tid < 8) {
            float s = red_s[tid];
#pragma unroll
            for (int w = 1; w < 8; w++) s += red_s[w * 8 + tid];
            rsum_s[tid] = s;
        }
        __syncthreads();

        // stores (float2, coalesced) using cached exps
#pragma unroll
        for (int i = 0; i < 8; i++) {
            const float inv = 1.0f / rsum_s[i];
            const float dv0 = d0[i], dv1 = d1[i];
            const size_t base = (size_t)(brow + gq * 8 + i) * NK + c0;
            *(float2*)&distances[base] = make_float2(dv0, dv1);
            *(float2*)&weighted[base]  = make_float2(
                dv0 * e0[i] * inv,
                dv1 * e1[i] * inv);
        }
        __syncthreads();   // protect rmin_s/rsum_s/red_s before next group
    }
}

// ---------------------------------------------------------------------------
extern "C" void kernel_launch(void* const* d_in, const int* in_sizes, int n_in,
                              void* d_out, int out_size)
{
    const float* x    = (const float*)d_in[0];
    const float* reps = (const float*)d_in[1];
    const float* W1   = (const float*)d_in[2];
    const float* b1   = (const float*)d_in[3];
    const float* W2   = (const float*)d_in[4];
    const float* b2   = (const float*)d_in[5];
    const float* W3   = (const float*)d_in[6];
    const float* b3   = (const float*)d_in[7];
    const float* W4   = (const float*)d_in[8];
    const float* b4   = (const float*)d_in[9];

    float* out       = (float*)d_out;
    float* weighted  = out;
    float* distances = out + (size_t)NB * NK;
    float* rec       = out + 2 * (size_t)NB * NK;
    float* emb       = out + 2 * (size_t)NB * NK + (size_t)NB * ND;

    float *xhi, *xlo, *hhi, *hlo, *ehi, *elo, *h2hi, *h2lo;
    float *w1hi, *w1lo, *w2hi, *w2lo, *w3hi, *w3lo, *w4hi, *w4lo;
    cudaGetSymbolAddress((void**)&xhi,  g_xhi);  cudaGetSymbolAddress((void**)&xlo,  g_xlo);
    cudaGetSymbolAddress((void**)&hhi,  g_hhi);  cudaGetSymbolAddress((void**)&hlo,  g_hlo);
    cudaGetSymbolAddress((void**)&ehi,  g_ehi);  cudaGetSymbolAddress((void**)&elo,  g_elo);
    cudaGetSymbolAddress((void**)&h2hi, g_h2hi); cudaGetSymbolAddress((void**)&h2lo, g_h2lo);
    cudaGetSymbolAddress((void**)&w1hi, g_w1hi); cudaGetSymbolAddress((void**)&w1lo, g_w1lo);
    cudaGetSymbolAddress((void**)&w2hi, g_w2hi); cudaGetSymbolAddress((void**)&w2lo, g_w2lo);
    cudaGetSymbolAddress((void**)&w3hi, g_w3hi); cudaGetSymbolAddress((void**)&w3lo, g_w3lo);
    cudaGetSymbolAddress((void**)&w4hi, g_w4hi); cudaGetSymbolAddress((void**)&w4lo, g_w4lo);

    // smem sizes: 3 stages * (2*MBLKS*1024 + 2*NBLKS*512)
    const int smem_g1 = 3 * (2 * 8 * 1024 + 2 * 8 * 512);    // 73728
    const int smem_g2 = 3 * (2 * 2 * 1024 + 2 * 4 * 512);    // 24576
    const int smem_g4 = 3 * (2 * 8 * 1024 + 2 * 16 * 512);   // 98304
    cudaFuncSetAttribute((const void*)mma_gemm<true, 1, 8, 8, 2>,
                         cudaFuncAttributeMaxDynamicSharedMemorySize, smem_g1);
    cudaFuncSetAttribute((const void*)mma_gemm<false, 2, 4, 2, 4>,
                         cudaFuncAttributeMaxDynamicSharedMemorySize, smem_g2);
    cudaFuncSetAttribute((const void*)mma_gemm<false, 0, 16, 8, 2>,
                         cudaFuncAttributeMaxDynamicSharedMemorySize, smem_g4);

    // second stream + fork/join events (capture-legal pattern; fresh per call,
    // no device-memory allocation, not destroyed mid-capture)
    cudaStream_t s2;
    cudaStreamCreateWithFlags(&s2, cudaStreamNonBlocking);
    cudaEvent_t evA, evB, evC, evD;
    cudaEventCreateWithFlags(&evA, cudaEventDisableTiming);
    cudaEventCreateWithFlags(&evB, cudaEventDisableTiming);
    cudaEventCreateWithFlags(&evC, cudaEventDisableTiming);
    cudaEventCreateWithFlags(&evD, cudaEventDisableTiming);

    // ---- fork 1: split_A (main) || split_B4 (s2) ----
    cudaEventRecord(evA, 0);
    cudaStreamWaitEvent(s2, evA, 0);

    split_A_kernel<<<dim3(13, NB / 32), 256>>>(x, xhi, xlo, ND, 98);
    {
        SplitBArgs a;
        a.W[0] = W1;   a.hi[0] = w1hi; a.lo[0] = w1lo;
        a.K[0] = ND;   a.N[0] = NH;    a.KB[0] = 98; a.gx[0] = 8;  a.gy[0] = 13;
        a.W[1] = W2;   a.hi[1] = w2hi; a.lo[1] = w2lo;
        a.K[1] = NH;   a.N[1] = NE;    a.KB[1] = 32; a.gx[1] = 1;  a.gy[1] = 4;
        a.W[2] = W3;   a.hi[2] = w3hi; a.lo[2] = w3lo;
        a.K[2] = NE;   a.N[2] = NH;    a.KB[2] = 4;  a.gx[2] = 8;  a.gy[2] = 1;
        a.W[3] = W4;   a.hi[3] = w4hi; a.lo[3] = w4lo;
        a.K[3] = NH;   a.N[3] = ND;    a.KB[3] = 32; a.gx[3] = 28; a.gy[3] = 4;
        split_B4_kernel<<<dim3(28, 13, 4), 256, 0, s2>>>(a);
    }
    cudaEventRecord(evB, s2);
    cudaStreamWaitEvent(0, evB, 0);

    // ---- GEMM chain (main stream) ----
    // h = relu(x @ W1 + b1)  -> h fragments          (128x64 tiles, 256 CTAs)
    mma_gemm<true, 1, 8, 8, 2><<<dim3(4, NB / 128), 256, smem_g1>>>(
        xhi, xlo, w1hi, w1lo, b1, nullptr, hhi, hlo, NH, 98, 32);
    // emb = h @ W2 + b2      -> normal emb + emb fragments (32x32 tiles, 256 CTAs)
    mma_gemm<false, 2, 4, 2, 4><<<dim3(1, NB / 32), 256, smem_g2>>>(
        hhi, hlo, w2hi, w2lo, b2, emb, ehi, elo, NE, 32, 4);

    // ---- fork 2: dist (s2) || G3->G4 (main) ----
    cudaEventRecord(evC, 0);
    cudaStreamWaitEvent(s2, evC, 0);
    dist_softmin_kernel<<<NB / 32, 256, 0, s2>>>(emb, reps, weighted, distances);

    // h2 = relu(emb @ W3 + b3) -> h2 fragments       (128x64 tiles, 256 CTAs)
    mma_gemm<true, 1, 8, 8, 2><<<dim3(4, NB / 128), 256, smem_g1>>>(
        ehi, elo, w3hi, w3lo, b3, nullptr, h2hi, h2lo, NH, 4, 32);
    // rec = h2 @ W4 + b4     -> normal output        (128x128 tiles, 448 CTAs)
    mma_gemm<false, 0, 16, 8, 2><<<dim3(7, NB / 128), 256, smem_g4>>>(
        h2hi, h2lo, w4hi, w4lo, b4, rec, nullptr, nullptr, ND, 32, 0);

    // ---- join s2 back into the main stream ----
    cudaEventRecord(evD, s2);
    cudaStreamWaitEvent(0, evD, 0);
}

// round 17
// speedup vs baseline: 1.3562x; 1.0613x over previous
#include <cuda_runtime.h>
#include <cstdint>
#include <math.h>

#define ALPHA 1000.0f
#define NB 8192
#define ND 784
#define NH 256
#define NE 32
#define NK 512

// ---------------------------------------------------------------------------
// Fragment-major hi/lo scratch (allocation-free rule: __device__ globals).
// A-frag layout: [mblk][KB][32 lanes][4]  (128 floats / block)
// B-frag layout: [nblk][KB][32 lanes][2]  (64 floats / block)
// ---------------------------------------------------------------------------
__device__ float g_xhi [NB * ND], g_xlo [NB * ND];     // x    A-frags, KB=98
__device__ float g_hhi [NB * NH], g_hlo [NB * NH];     // h    A-frags, KB=32
__device__ float g_ehi [NB * NE], g_elo [NB * NE];     // emb  A-frags, KB=4
__device__ float g_h2hi[NB * NH], g_h2lo[NB * NH];     // h2   A-frags, KB=32
__device__ float g_w1hi[32 * 98 * 64],  g_w1lo[32 * 98 * 64];    // W1 (N=256)
__device__ float g_w2hi[4 * 32 * 64],   g_w2lo[4 * 32 * 64];     // W2 (NPAD=32)
__device__ float g_w3hi[32 * 4 * 64],   g_w3lo[32 * 4 * 64];     // W3 (N=256)
__device__ float g_w4hi[112 * 32 * 64], g_w4lo[112 * 32 * 64];   // W4 (NPAD=896)

// ---------------------------------------------------------------------------
// helpers (baseline PTX only)
// ---------------------------------------------------------------------------
__device__ __forceinline__ uint32_t tf32_round(float x) {
    uint32_t u;
    asm("cvt.rna.tf32.f32 %0, %1;" : "=r"(u) : "f"(x));
    return u;
}
__device__ __forceinline__ void mma_tf32(float* d, const uint32_t* a, const uint32_t* b) {
    asm volatile(
        "mma.sync.aligned.m16n8k8.row.col.f32.tf32.tf32.f32 "
        "{%0,%1,%2,%3}, {%4,%5,%6,%7}, {%8,%9}, {%0,%1,%2,%3};"
        : "+f"(d[0]), "+f"(d[1]), "+f"(d[2]), "+f"(d[3])
        : "r"(a[0]), "r"(a[1]), "r"(a[2]), "r"(a[3]), "r"(b[0]), "r"(b[1]));
}
__device__ __forceinline__ uint32_t smem_u32(const void* p) {
    uint32_t a;
    asm("{ .reg .u64 t; cvta.to.shared.u64 t, %1; cvt.u32.u64 %0, t; }" : "=r"(a) : "l"(p));
    return a;
}
__device__ __forceinline__ void cp16(uint32_t dst, const void* src) {
    asm volatile("cp.async.cg.shared.global [%0], [%1], 16;" :: "r"(dst), "l"(src));
}

// write one value into A-fragment hi/lo buffers (for the next GEMM)
__device__ __forceinline__ void write_frag(float v, int m, int k, int KB,
                                           float* ghi, float* glo) {
    uint32_t hi = tf32_round(v);
    uint32_t lo = tf32_round(v - __uint_as_float(hi));
    const int mblk = m >> 4, kblk = k >> 3;
    const int ln   = ((m & 7) << 2) | (k & 3);
    const int slot = ((m >> 3) & 1) | (((k >> 2) & 1) << 1);
    const size_t o = (((size_t)mblk * KB + kblk) * 32 + ln) * 4 + slot;
    ((uint32_t*)ghi)[o] = hi;
    ((uint32_t*)glo)[o] = lo;
}

// ---------------------------------------------------------------------------
// split_A: A[M,K] row-major -> hi/lo A-fragments. Tile 32m x 64k per block.
// ---------------------------------------------------------------------------
__global__ __launch_bounds__(256) void split_A_kernel(
    const float* __restrict__ A, float* __restrict__ hi, float* __restrict__ lo,
    int K, int KB)
{
    __shared__ float s[32][65];
    const int tid = threadIdx.x;
    const int k0 = blockIdx.x * 64;
    const int m0 = blockIdx.y * 32;
#pragma unroll
    for (int i = 0; i < 8; i++) {
        const int idx = tid + i * 256;
        const int r = idx >> 6, cc = idx & 63;
        const int k = k0 + cc;
        s[r][cc] = (k < K) ? A[(size_t)(m0 + r) * K + k] : 0.f;
    }
    __syncthreads();
    const int mblk0 = blockIdx.y * 2, kblk0 = blockIdx.x * 8;
#pragma unroll
    for (int i = 0; i < 2; i++) {
        const int slot = tid + i * 256;       // 0..511
        const int mb = slot >> 8, kb = (slot >> 5) & 7, ln = slot & 31;
        if (kblk0 + kb < KB) {
            const int gg = ln >> 2, cc = ln & 3;
            const int mr = mb * 16 + gg, kc = kb * 8 + cc;
            const float v0 = s[mr][kc],     v1 = s[mr + 8][kc];
            const float v2 = s[mr][kc + 4], v3 = s[mr + 8][kc + 4];
            uint4 h4, l4;
            h4.x = tf32_round(v0); l4.x = tf32_round(v0 - __uint_as_float(h4.x));
            h4.y = tf32_round(v1); l4.y = tf32_round(v1 - __uint_as_float(h4.y));
            h4.z = tf32_round(v2); l4.z = tf32_round(v2 - __uint_as_float(h4.z));
            h4.w = tf32_round(v3); l4.w = tf32_round(v3 - __uint_as_float(h4.w));
            const size_t o = (((size_t)(mblk0 + mb) * KB + kblk0 + kb) * 32 + ln) * 4;
            *(uint4*)&hi[o] = h4;
            *(uint4*)&lo[o] = l4;
        }
    }
}

// ---------------------------------------------------------------------------
// merged split_B for all 4 weights: W[K,N] -> hi/lo B-fragments (pad to NPAD).
// ---------------------------------------------------------------------------
struct SplitBArgs {
    const float* W[4];
    float* hi[4];
    float* lo[4];
    int K[4], N[4], KB[4], gx[4], gy[4];
};

__global__ __launch_bounds__(256) void split_B4_kernel(SplitBArgs a)
{
    const int z = blockIdx.z;
    if ((int)blockIdx.x >= a.gx[z] || (int)blockIdx.y >= a.gy[z]) return;
    const float* __restrict__ W = a.W[z];
    float* __restrict__ hi = a.hi[z];
    float* __restrict__ lo = a.lo[z];
    const int K = a.K[z], N = a.N[z], KB = a.KB[z];

    __shared__ float s[64][33];
    const int tid = threadIdx.x;
    const int n0 = blockIdx.x * 32;
    const int k0 = blockIdx.y * 64;
#pragma unroll
    for (int i = 0; i < 8; i++) {
        const int idx = tid + i * 256;
        const int r = idx >> 5, cc = idx & 31;
        const int k = k0 + r, n = n0 + cc;
        s[r][cc] = (k < K && n < N) ? W[(size_t)k * N + n] : 0.f;
    }
    __syncthreads();
    const int nblk0 = blockIdx.x * 4, kblk0 = blockIdx.y * 8;
#pragma unroll
    for (int i = 0; i < 4; i++) {
        const int slot = tid + i * 256;       // 0..1023
        const int nb = slot >> 8, kb = (slot >> 5) & 7, ln = slot & 31;
        if (kblk0 + kb < KB) {
            const int gg = ln >> 2, cc = ln & 3;
            const float b0 = s[kb * 8 + cc][nb * 8 + gg];
            const float b1 = s[kb * 8 + cc + 4][nb * 8 + gg];
            uint2 h2, l2;
            h2.x = tf32_round(b0); l2.x = tf32_round(b0 - __uint_as_float(h2.x));
            h2.y = tf32_round(b1); l2.y = tf32_round(b1 - __uint_as_float(h2.y));
            const size_t o = (((size_t)(nblk0 + nb) * KB + kblk0 + kb) * 32 + ln) * 2;
            *(uint2*)&hi[o] = h2;
            *(uint2*)&lo[o] = l2;
        }
    }
}

// ---------------------------------------------------------------------------
// 3xTF32 GEMM on pre-split fragments, 3-stage cp.async pipeline.
// CTA tile (MBLKS*16) x (NBLKS*8), 256 threads = 8 warps (2M x 4N).
// TERMS=3: D = Ah*Bh + Ah*Bl + Al*Bh (exact path).
// TERMS=2: D = Ah*Bh + Ah*Bl (A_lo never staged; ~2^-12 rel err; rec-only).
// smem: 3 stages x (A_hi + A_lo? + Bhi + Blo).
// OUTMODE: 0 = normal C, 1 = A-frags of next gemm, 2 = both.
// ---------------------------------------------------------------------------
template <bool RELU, int OUTMODE, int NBLKS, int MBLKS, int OCC, int TERMS>
__global__ __launch_bounds__(256, OCC) void mma_gemm(
    const float* __restrict__ Ahi, const float* __restrict__ Alo,
    const float* __restrict__ Bhi, const float* __restrict__ Blo,
    const float* __restrict__ bias,
    float* __restrict__ Cn, float* __restrict__ Chi, float* __restrict__ Clo,
    int N, int KB, int KBOUT)
{
    constexpr int NTW = NBLKS / 4;    // nblks per warp
    constexpr int MT  = MBLKS / 2;    // mtiles (16 rows each) per warp
    constexpr int A_BYTES  = MBLKS * 1024;
    constexpr int A_LO_B   = (TERMS == 3) ? A_BYTES : 0;
    constexpr int B_BYTES  = NBLKS * 512;
    constexpr int OFF_BHI  = A_BYTES + A_LO_B;
    constexpr int OFF_BLO  = OFF_BHI + B_BYTES;
    constexpr int STAGE    = OFF_BLO + B_BYTES;

    extern __shared__ char smem[];
    const uint32_t sb32 = smem_u32(smem);
    const int tid = threadIdx.x, wid = tid >> 5, lane = tid & 31;
    const int wm = wid & 1, wn = wid >> 1;
    const int g = lane >> 2, c = lane & 3;
    const int m0 = blockIdx.y * MBLKS * 16, n0 = blockIdx.x * NBLKS * 8;
    const int mblk0 = blockIdx.y * MBLKS, nblk0 = blockIdx.x * NBLKS;

    float acc[MT][NTW][4];
#pragma unroll
    for (int mt = 0; mt < MT; mt++)
#pragma unroll
        for (int nt = 0; nt < NTW; nt++)
#pragma unroll
            for (int i = 0; i < 4; i++) acc[mt][nt][i] = 0.f;

    const int nch = KB >> 1;

    auto issue = [&](int t) {
        const uint32_t s = sb32 + (t % 3) * STAGE;
        const int kb0 = t * 2;
        // A: MBLKS*64 cp16 (MBLKS mblks x 2 kblks x 128 floats)
#pragma unroll
        for (int idx = tid; idx < MBLKS * 64; idx += 256) {
            const int mb = idx >> 6, off = idx & 63;
            const size_t go = ((size_t)(mblk0 + mb) * KB + kb0) * 128 + off * 4;
            cp16(s + idx * 16, Ahi + go);
            if (TERMS == 3) cp16(s + A_BYTES + idx * 16, Alo + go);
        }
        // B: NBLKS*32 cp16 (NBLKS nblks x 2 kblks x 64 floats)
#pragma unroll
        for (int idx = tid; idx < NBLKS * 32; idx += 256) {
            const int nb = idx >> 5, off = idx & 31;
            const size_t go = ((size_t)(nblk0 + nb) * KB + kb0) * 64 + off * 4;
            cp16(s + OFF_BHI + idx * 16, Bhi + go);
            cp16(s + OFF_BLO + idx * 16, Blo + go);
        }
    };

    int issued = 0;
    const int pre = (nch < 2) ? nch : 2;
    for (; issued < pre; issued++) {
        issue(issued);
        asm volatile("cp.async.commit_group;");
    }

    for (int t = 0; t < nch; t++) {
        if (issued < nch) {
            issue(issued);
            asm volatile("cp.async.commit_group;");
            issued++;
        }
        const int pending = issued - t - 1;
        if (pending >= 2)      asm volatile("cp.async.wait_group 2;");
        else if (pending == 1) asm volatile("cp.async.wait_group 1;");
        else                   asm volatile("cp.async.wait_group 0;");
        __syncthreads();

        const char* s = smem + (t % 3) * STAGE;
#pragma unroll
        for (int ks = 0; ks < 2; ks++) {
            uint4 ah[MT], al[MT];
#pragma unroll
            for (int mt = 0; mt < MT; mt++) {
                const int off = (((wm * MT + mt) * 2 + ks) * 32 + lane) * 16;
                ah[mt] = *(const uint4*)(s + off);
                if (TERMS == 3) al[mt] = *(const uint4*)(s + A_BYTES + off);
            }
            uint2 bh[NTW], bl[NTW];
#pragma unroll
            for (int nt = 0; nt < NTW; nt++) {
                const int off = (((wn * NTW + nt) * 2 + ks) * 32 + lane) * 8;
                bh[nt] = *(const uint2*)(s + OFF_BHI + off);
                bl[nt] = *(const uint2*)(s + OFF_BLO + off);
            }
#pragma unroll
            for (int mt = 0; mt < MT; mt++)
#pragma unroll
                for (int nt = 0; nt < NTW; nt++) {
                    mma_tf32(acc[mt][nt], (const uint32_t*)&ah[mt], (const uint32_t*)&bh[nt]);
                    mma_tf32(acc[mt][nt], (const uint32_t*)&ah[mt], (const uint32_t*)&bl[nt]);
                    if (TERMS == 3)
                        mma_tf32(acc[mt][nt], (const uint32_t*)&al[mt], (const uint32_t*)&bh[nt]);
                }
        }
        __syncthreads();
    }

    // ---- epilogue ----
#pragma unroll
    for (int nt = 0; nt < NTW; nt++) {
        const int col = n0 + (wn * NTW + nt) * 8 + 2 * c;
        if (col < N) {
            const float bx = __ldg(&bias[col]);
            const float by = __ldg(&bias[col + 1]);
#pragma unroll
            for (int mt = 0; mt < MT; mt++) {
                const int row = m0 + (wm * MT + mt) * 16 + g;
                float v00 = acc[mt][nt][0] + bx;
                float v01 = acc[mt][nt][1] + by;
                float v10 = acc[mt][nt][2] + bx;
                float v11 = acc[mt][nt][3] + by;
                if (RELU) {
                    v00 = fmaxf(v00, 0.f); v01 = fmaxf(v01, 0.f);
                    v10 = fmaxf(v10, 0.f); v11 = fmaxf(v11, 0.f);
                }
                if (OUTMODE == 0 || OUTMODE == 2) {
                    *(float2*)&Cn[(size_t)row * N + col]       = make_float2(v00, v01);
                    *(float2*)&Cn[(size_t)(row + 8) * N + col] = make_float2(v10, v11);
                }
                if (OUTMODE == 1 || OUTMODE == 2) {
                    write_frag(v00, row,     col,     KBOUT, Chi, Clo);
                    write_frag(v01, row,     col + 1, KBOUT, Chi, Clo);
                    write_frag(v10, row + 8, col,     KBOUT, Chi, Clo);
                    write_frag(v11, row + 8, col + 1, KBOUT, Chi, Clo);
                }
            }
        }
    }
}

// ---------------------------------------------------------------------------
// Dist v4: dot-product form, reps register-resident (2 clusters/thread),
// exp computed ONCE per element (cached in regs) via __expf.
// Block = 256 threads, 32 rows (4 groups of 8); 256 blocks fill the chip.
// ---------------------------------------------------------------------------
__global__ __launch_bounds__(256) void dist_softmin_kernel(
    const float* __restrict__ emb, const float* __restrict__ reps,
    float* __restrict__ weighted, float* __restrict__ distances)
{
    __shared__ float emb_s[32 * NE];     // 4KB
    __shared__ float en_s[32];
    __shared__ float red_s[8 * 8];       // [warp][row-in-group]
    __shared__ float rmin_s[8], rsum_s[8];

    const int tid  = threadIdx.x;
    const int wid  = tid >> 5;
    const int lane = tid & 31;
    const int brow = blockIdx.x * 32;
    const int c0   = tid * 2;

    // load 2 cluster reps into registers + norms
    float r0[NE], r1[NE];
    float rn0 = 0.f, rn1 = 0.f;
    const float4* rp0 = (const float4*)(reps + (size_t)c0 * NE);
    const float4* rp1 = (const float4*)(reps + (size_t)(c0 + 1) * NE);
#pragma unroll
    for (int e4 = 0; e4 < 8; e4++) {
        float4 a = rp0[e4], b = rp1[e4];
        r0[e4*4+0] = a.x; r0[e4*4+1] = a.y; r0[e4*4+2] = a.z; r0[e4*4+3] = a.w;
        r1[e4*4+0] = b.x; r1[e4*4+1] = b.y; r1[e4*4+2] = b.z; r1[e4*4+3] = b.w;
        rn0 = fmaf(a.x, a.x, rn0); rn0 = fmaf(a.y, a.y, rn0);
        rn0 = fmaf(a.z, a.z, rn0); rn0 = fmaf(a.w, a.w, rn0);
        rn1 = fmaf(b.x, b.x, rn1); rn1 = fmaf(b.y, b.y, rn1);
        rn1 = fmaf(b.z, b.z, rn1); rn1 = fmaf(b.w, b.w, rn1);
    }

    // stage 32 emb rows
    const float4* embg = (const float4*)(emb + (size_t)brow * NE);
    {
        const int idx = tid;   // 256 threads cover 32*32/4 = 256 float4s
        ((float4*)emb_s)[idx] = embg[idx];
    }
    __syncthreads();
    // row norms
    if (tid < 32) {
        const float4* ep = (const float4*)(emb_s + tid * NE);
        float s = 0.f;
#pragma unroll
        for (int e4 = 0; e4 < 8; e4++) {
            float4 v = ep[e4];
            s = fmaf(v.x, v.x, s); s = fmaf(v.y, v.y, s);
            s = fmaf(v.z, v.z, s); s = fmaf(v.w, v.w, s);
        }
        en_s[tid] = s;
    }
    __syncthreads();

#pragma unroll 1
    for (int gq = 0; gq < 4; gq++) {
        float d0[8], d1[8];
#pragma unroll
        for (int i = 0; i < 8; i++) {
            const int r = gq * 8 + i;
            const float4* ep = (const float4*)(emb_s + r * NE);
            float dot0 = 0.f, dot1 = 0.f;
#pragma unroll
            for (int e4 = 0; e4 < 8; e4++) {
                float4 ev = ep[e4];   // broadcast LDS.128
                dot0 = fmaf(ev.x, r0[e4*4+0], dot0);
                dot0 = fmaf(ev.y, r0[e4*4+1], dot0);
                dot0 = fmaf(ev.z, r0[e4*4+2], dot0);
                dot0 = fmaf(ev.w, r0[e4*4+3], dot0);
                dot1 = fmaf(ev.x, r1[e4*4+0], dot1);
                dot1 = fmaf(ev.y, r1[e4*4+1], dot1);
                dot1 = fmaf(ev.z, r1[e4*4+2], dot1);
                dot1 = fmaf(ev.w, r1[e4*4+3], dot1);
            }
            const float en = en_s[r];
            d0[i] = fmaf(-2.f, dot0, en + rn0);
            d1[i] = fmaf(-2.f, dot1, en + rn1);
        }

        // block-wide min per row
#pragma unroll
        for (int i = 0; i < 8; i++) {
            float v = fminf(d0[i], d1[i]);
#pragma unroll
            for (int o = 16; o > 0; o >>= 1)
                v = fminf(v, __shfl_xor_sync(0xFFFFFFFF, v, o));
            if (lane == 0) red_s[wid * 8 + i] = v;
        }
        __syncthreads();
        if (tid < 8) {
            float m = red_s[tid];
#pragma unroll
            for (int w = 1; w < 8; w++) m = fminf(m, red_s[w * 8 + tid]);
            rmin_s[tid] = m;
        }
        __syncthreads();

        // block-wide exp-sum per row; exp cached in registers (single MUFU each)
        float e0[8], e1[8];
#pragma unroll
        for (int i = 0; i < 8; i++) {
            const float mv = rmin_s[i];
            e0[i] = __expf(-ALPHA * (d0[i] - mv));
            e1[i] = __expf(-ALPHA * (d1[i] - mv));
            float ps = e0[i] + e1[i];
#pragma unroll
            for (int o = 16; o > 0; o >>= 1)
                ps += __shfl_xor_sync(0xFFFFFFFF, ps, o);
            if (lane == 0) red_s[wid * 8 + i] = ps;
        }
        __syncthreads();
        if (tid < 8) {
            float s = red_s[tid];
#pragma unroll
            for (int w = 1; w < 8; w++) s += red_s[w * 8 + tid];
            rsum_s[tid] = s;
        }
        __syncthreads();

        // stores (float2, coalesced) using cached exps
#pragma unroll
        for (int i = 0; i < 8; i++) {
            const float inv = 1.0f / rsum_s[i];
            const float dv0 = d0[i], dv1 = d1[i];
            const size_t base = (size_t)(brow + gq * 8 + i) * NK + c0;
            *(float2*)&distances[base] = make_float2(dv0, dv1);
            *(float2*)&weighted[base]  = make_float2(
                dv0 * e0[i] * inv,
                dv1 * e1[i] * inv);
        }
        __syncthreads();   // protect rmin_s/rsum_s/red_s before next group
    }
}

// ---------------------------------------------------------------------------
extern "C" void kernel_launch(void* const* d_in, const int* in_sizes, int n_in,
                              void* d_out, int out_size)
{
    const float* x    = (const float*)d_in[0];
    const float* reps = (const float*)d_in[1];
    const float* W1   = (const float*)d_in[2];
    const float* b1   = (const float*)d_in[3];
    const float* W2   = (const float*)d_in[4];
    const float* b2   = (const float*)d_in[5];
    const float* W3   = (const float*)d_in[6];
    const float* b3   = (const float*)d_in[7];
    const float* W4   = (const float*)d_in[8];
    const float* b4   = (const float*)d_in[9];

    float* out       = (float*)d_out;
    float* weighted  = out;
    float* distances = out + (size_t)NB * NK;
    float* rec       = out + 2 * (size_t)NB * NK;
    float* emb       = out + 2 * (size_t)NB * NK + (size_t)NB * ND;

    float *xhi, *xlo, *hhi, *hlo, *ehi, *elo, *h2hi, *h2lo;
    float *w1hi, *w1lo, *w2hi, *w2lo, *w3hi, *w3lo, *w4hi, *w4lo;
    cudaGetSymbolAddress((void**)&xhi,  g_xhi);  cudaGetSymbolAddress((void**)&xlo,  g_xlo);
    cudaGetSymbolAddress((void**)&hhi,  g_hhi);  cudaGetSymbolAddress((void**)&hlo,  g_hlo);
    cudaGetSymbolAddress((void**)&ehi,  g_ehi);  cudaGetSymbolAddress((void**)&elo,  g_elo);
    cudaGetSymbolAddress((void**)&h2hi, g_h2hi); cudaGetSymbolAddress((void**)&h2lo, g_h2lo);
    cudaGetSymbolAddress((void**)&w1hi, g_w1hi); cudaGetSymbolAddress((void**)&w1lo, g_w1lo);
    cudaGetSymbolAddress((void**)&w2hi, g_w2hi); cudaGetSymbolAddress((void**)&w2lo, g_w2lo);
    cudaGetSymbolAddress((void**)&w3hi, g_w3hi); cudaGetSymbolAddress((void**)&w3lo, g_w3lo);
    cudaGetSymbolAddress((void**)&w4hi, g_w4hi); cudaGetSymbolAddress((void**)&w4lo, g_w4lo);

    // smem sizes: 3 stages * stage
    const int smem_g1 = 3 * (2 * 8 * 1024 + 2 * 8 * 512);    // 73728 (TERMS=3)
    const int smem_g2 = 3 * (2 * 2 * 1024 + 2 * 4 * 512);    // 24576 (TERMS=3)
    const int smem_g4 = 3 * (8 * 1024 + 2 * 16 * 512);       // 73728 (TERMS=2)
    cudaFuncSetAttribute((const void*)mma_gemm<true, 1, 8, 8, 2, 3>,
                         cudaFuncAttributeMaxDynamicSharedMemorySize, smem_g1);
    cudaFuncSetAttribute((const void*)mma_gemm<false, 2, 4, 2, 4, 3>,
                         cudaFuncAttributeMaxDynamicSharedMemorySize, smem_g2);
    cudaFuncSetAttribute((const void*)mma_gemm<false, 0, 16, 8, 2, 2>,
                         cudaFuncAttributeMaxDynamicSharedMemorySize, smem_g4);

    // second stream + fork/join events (capture-legal pattern; fresh per call,
    // no device-memory allocation, not destroyed mid-capture)
    cudaStream_t s2;
    cudaStreamCreateWithFlags(&s2, cudaStreamNonBlocking);
    cudaEvent_t evA, evB, evC, evD;
    cudaEventCreateWithFlags(&evA, cudaEventDisableTiming);
    cudaEventCreateWithFlags(&evB, cudaEventDisableTiming);
    cudaEventCreateWithFlags(&evC, cudaEventDisableTiming);
    cudaEventCreateWithFlags(&evD, cudaEventDisableTiming);

    // ---- fork 1: split_A (main) || split_B4 (s2) ----
    cudaEventRecord(evA, 0);
    cudaStreamWaitEvent(s2, evA, 0);

    split_A_kernel<<<dim3(13, NB / 32), 256>>>(x, xhi, xlo, ND, 98);
    {
        SplitBArgs a;
        a.W[0] = W1;   a.hi[0] = w1hi; a.lo[0] = w1lo;
        a.K[0] = ND;   a.N[0] = NH;    a.KB[0] = 98; a.gx[0] = 8;  a.gy[0] = 13;
        a.W[1] = W2;   a.hi[1] = w2hi; a.lo[1] = w2lo;
        a.K[1] = NH;   a.N[1] = NE;    a.KB[1] = 32; a.gx[1] = 1;  a.gy[1] = 4;
        a.W[2] = W3;   a.hi[2] = w3hi; a.lo[2] = w3lo;
        a.K[2] = NE;   a.N[2] = NH;    a.KB[2] = 4;  a.gx[2] = 8;  a.gy[2] = 1;
        a.W[3] = W4;   a.hi[3] = w4hi; a.lo[3] = w4lo;
        a.K[3] = NH;   a.N[3] = ND;    a.KB[3] = 32; a.gx[3] = 28; a.gy[3] = 4;
        split_B4_kernel<<<dim3(28, 13, 4), 256, 0, s2>>>(a);
    }
    cudaEventRecord(evB, s2);
    cudaStreamWaitEvent(0, evB, 0);

    // ---- GEMM chain (main stream) ----
    // h = relu(x @ W1 + b1)  -> h fragments          (128x64 tiles, 256 CTAs)
    mma_gemm<true, 1, 8, 8, 2, 3><<<dim3(4, NB / 128), 256, smem_g1>>>(
        xhi, xlo, w1hi, w1lo, b1, nullptr, hhi, hlo, NH, 98, 32);
    // emb = h @ W2 + b2      -> normal emb + emb fragments (32x32 tiles, 256 CTAs)
    mma_gemm<false, 2, 4, 2, 4, 3><<<dim3(1, NB / 32), 256, smem_g2>>>(
        hhi, hlo, w2hi, w2lo, b2, emb, ehi, elo, NE, 32, 4);

    // ---- fork 2: dist (s2) || G3->G4 (main) ----
    cudaEventRecord(evC, 0);
    cudaStreamWaitEvent(s2, evC, 0);
    dist_softmin_kernel<<<NB / 32, 256, 0, s2>>>(emb, reps, weighted, distances);

    // h2 = relu(emb @ W3 + b3) -> h2 fragments       (128x64 tiles, 256 CTAs)
    mma_gemm<true, 1, 8, 8, 2, 3><<<dim3(4, NB / 128), 256, smem_g1>>>(
        ehi, elo, w3hi, w3lo, b3, nullptr, h2hi, h2lo, NH, 4, 32);
    // rec = h2 @ W4 + b4     -> normal output (TERMS=2: rec-only precision)
    mma_gemm<false, 0, 16, 8, 2, 2><<<dim3(7, NB / 128), 256, smem_g4>>>(
        h2hi, h2lo, w4hi, w4lo, b4, rec, nullptr, nullptr, ND, 32, 0);

    // ---- join s2 back into the main stream ----
    cudaEventRecord(evD, s2);
    cudaStreamWaitEvent(0, evD, 0);
}